// round 1
// baseline (speedup 1.0000x reference)
#include <cuda_runtime.h>

#define BB 8
#define CC 512
#define DD 64
#define NN 4096

// Scratch (device globals; allocation-free per harness rules). ~19 MB total.
__device__ float g_Qf[BB * DD * NN];        // 8 MB  delu(Q)
__device__ float g_Kf[BB * DD * NN];        // 8 MB  delu(K)
__device__ float g_Ksum[BB * DD];           // row sums of Kf
__device__ float g_KXp[2 * BB * DD * CC];   // 2 MB  split-K partials of Kf @ X^T
__device__ float g_KV[BB * DD * CC];        // 1 MB  KV = KX @ wv^T + bv (x) Ksum

__device__ __forceinline__ float delu_f(float v) {
    // 10*relu(v) + exp(10*min(v,0)) ; continuous at 0 (both give 1)
    return v > 0.f ? fmaf(10.f, v, 1.f) : __expf(10.f * v);
}

// ---------------------------------------------------------------------------
// K1: Qraw/Kraw = [wq;wk] @ X  per batch, then delu -> g_Qf / g_Kf
// Tile: BM=128 (rows 0..63 = Q, 64..127 = K), BN=128, BK=32. 256 thr, 8x8 micro.
// grid: (NN/128, BB)
// ---------------------------------------------------------------------------
__global__ __launch_bounds__(256) void k1_qk(
    const float* __restrict__ x,  const float* __restrict__ wq,
    const float* __restrict__ bq, const float* __restrict__ wk,
    const float* __restrict__ bk)
{
    const int b  = blockIdx.y;
    const int n0 = blockIdx.x * 128;
    __shared__ float Ws[128][36];   // [m][kk] (pad 36 keeps float4 alignment)
    __shared__ float Xs[32][128];   // [kk][n]
    const int tid = threadIdx.x;
    const int tm = (tid / 16) * 8;
    const int tn = (tid % 16) * 8;
    float acc[8][8];
    #pragma unroll
    for (int i = 0; i < 8; i++)
        #pragma unroll
        for (int j = 0; j < 8; j++) acc[i][j] = 0.f;

    const float* xb = x + (size_t)b * CC * NN;

    for (int k0 = 0; k0 < CC; k0 += 32) {
        // W tile: 128x32 = 1024 float4 loads (4/thread)
        #pragma unroll
        for (int r = 0; r < 4; r++) {
            int idx = tid + r * 256;        // 0..1023
            int m   = idx >> 3;             // 0..127
            int c4  = idx & 7;              // 0..7
            const float* wrow = (m < 64) ? (wq + (size_t)m * CC)
                                         : (wk + (size_t)(m - 64) * CC);
            float4 v = *(const float4*)(wrow + k0 + c4 * 4);
            *(float4*)&Ws[m][c4 * 4] = v;
        }
        // X tile: 32x128 = 1024 float4 (4/thread)
        #pragma unroll
        for (int r = 0; r < 4; r++) {
            int idx = tid + r * 256;
            int kk  = idx >> 5;             // 0..31
            int n4  = idx & 31;             // 0..31
            float4 v = *(const float4*)(xb + (size_t)(k0 + kk) * NN + n0 + n4 * 4);
            *(float4*)&Xs[kk][n4 * 4] = v;
        }
        __syncthreads();
        #pragma unroll
        for (int kk = 0; kk < 32; kk++) {
            float a[8], q[8];
            #pragma unroll
            for (int i = 0; i < 8; i++) a[i] = Ws[tm + i][kk];
            *(float4*)&q[0] = *(float4*)&Xs[kk][tn];
            *(float4*)&q[4] = *(float4*)&Xs[kk][tn + 4];
            #pragma unroll
            for (int i = 0; i < 8; i++)
                #pragma unroll
                for (int j = 0; j < 8; j++)
                    acc[i][j] = fmaf(a[i], q[j], acc[i][j]);
        }
        __syncthreads();
    }

    #pragma unroll
    for (int i = 0; i < 8; i++) {
        int m = tm + i;
        float bias = (m < 64) ? bq[m] : bk[m - 64];
        float* dst = (m < 64) ? (g_Qf + ((size_t)b * DD + m) * NN)
                              : (g_Kf + ((size_t)b * DD + (m - 64)) * NN);
        #pragma unroll
        for (int j = 0; j < 8; j++)
            dst[n0 + tn + j] = delu_f(acc[i][j] + bias);
    }
}

// ---------------------------------------------------------------------------
// Ksum: g_Ksum[b][m] = sum_n g_Kf[b][m][n].  grid (DD, BB), 256 thr.
// ---------------------------------------------------------------------------
__global__ __launch_bounds__(256) void k_ksum()
{
    const int m = blockIdx.x, b = blockIdx.y;
    const float* src = g_Kf + ((size_t)b * DD + m) * NN;
    float s = 0.f;
    for (int i = threadIdx.x; i < NN; i += 256) s += src[i];
    __shared__ float red[256];
    red[threadIdx.x] = s;
    __syncthreads();
    for (int off = 128; off > 0; off >>= 1) {
        if (threadIdx.x < off) red[threadIdx.x] += red[threadIdx.x + off];
        __syncthreads();
    }
    if (threadIdx.x == 0) g_Ksum[b * DD + m] = red[0];
}

// ---------------------------------------------------------------------------
// K2: KXp[s][b][m][e] = sum_{n in split s} Kf[b][m][n] * x[b][e][n]
// M=64, N=64 e-tile, K=2048 per split. grid (CC/64, BB, 2), 256 thr, 4x4 micro.
// ---------------------------------------------------------------------------
__global__ __launch_bounds__(256) void k2_kx(const float* __restrict__ x)
{
    const int e0 = blockIdx.x * 64, b = blockIdx.y, s = blockIdx.z;
    const int nbase = s * 2048;
    __shared__ float As[64][33];    // Kf[m][n-tile]
    __shared__ float Bs[64][33];    // x[e][n-tile]
    const int tid = threadIdx.x;
    const int tm = (tid / 16) * 4;
    const int te = (tid % 16) * 4;
    float acc[4][4];
    #pragma unroll
    for (int i = 0; i < 4; i++)
        #pragma unroll
        for (int j = 0; j < 4; j++) acc[i][j] = 0.f;

    const float* kf = g_Kf + (size_t)b * DD * NN;
    const float* xb = x + (size_t)b * CC * NN;

    for (int k0 = 0; k0 < 2048; k0 += 32) {
        #pragma unroll
        for (int r = 0; r < 8; r++) {
            int idx = tid + r * 256;        // 0..2047
            int m   = idx >> 5;             // 0..63
            int kk  = idx & 31;
            As[m][kk] = kf[(size_t)m * NN + nbase + k0 + kk];
            Bs[m][kk] = xb[(size_t)(e0 + m) * NN + nbase + k0 + kk];
        }
        __syncthreads();
        #pragma unroll
        for (int kk = 0; kk < 32; kk++) {
            float a[4], q[4];
            #pragma unroll
            for (int i = 0; i < 4; i++) a[i] = As[tm + i][kk];
            #pragma unroll
            for (int j = 0; j < 4; j++) q[j] = Bs[te + j][kk];
            #pragma unroll
            for (int i = 0; i < 4; i++)
                #pragma unroll
                for (int j = 0; j < 4; j++)
                    acc[i][j] = fmaf(a[i], q[j], acc[i][j]);
        }
        __syncthreads();
    }

    float* dst = g_KXp + ((size_t)(s * BB + b) * DD) * CC;
    #pragma unroll
    for (int i = 0; i < 4; i++)
        #pragma unroll
        for (int j = 0; j < 4; j++)
            dst[(size_t)(tm + i) * CC + e0 + te + j] = acc[i][j];
}

// ---------------------------------------------------------------------------
// K3: KV[b][m][c] = sum_e (KXp0+KXp1)[b][m][e] * wv[c][e] + bv[c]*Ksum[b][m]
// grid (CC/64, BB), 256 thr, 4x4 micro, K=512.
// ---------------------------------------------------------------------------
__global__ __launch_bounds__(256) void k3_kv(
    const float* __restrict__ wv, const float* __restrict__ bv)
{
    const int c0 = blockIdx.x * 64, b = blockIdx.y;
    __shared__ float As[64][33];    // KX[m][e-tile]
    __shared__ float Bs[64][33];    // wv[c][e-tile]
    const int tid = threadIdx.x;
    const int tm = (tid / 16) * 4;
    const int tc = (tid % 16) * 4;
    float acc[4][4];
    #pragma unroll
    for (int i = 0; i < 4; i++)
        #pragma unroll
        for (int j = 0; j < 4; j++) acc[i][j] = 0.f;

    const float* kx0 = g_KXp + ((size_t)b * DD) * CC;
    const float* kx1 = g_KXp + ((size_t)(BB + b) * DD) * CC;

    for (int k0 = 0; k0 < CC; k0 += 32) {
        #pragma unroll
        for (int r = 0; r < 8; r++) {
            int idx = tid + r * 256;
            int m   = idx >> 5;
            int kk  = idx & 31;
            As[m][kk] = kx0[(size_t)m * CC + k0 + kk] + kx1[(size_t)m * CC + k0 + kk];
            Bs[m][kk] = wv[(size_t)(c0 + m) * CC + k0 + kk];
        }
        __syncthreads();
        #pragma unroll
        for (int kk = 0; kk < 32; kk++) {
            float a[4], q[4];
            #pragma unroll
            for (int i = 0; i < 4; i++) a[i] = As[tm + i][kk];
            #pragma unroll
            for (int j = 0; j < 4; j++) q[j] = Bs[tc + j][kk];
            #pragma unroll
            for (int i = 0; i < 4; i++)
                #pragma unroll
                for (int j = 0; j < 4; j++)
                    acc[i][j] = fmaf(a[i], q[j], acc[i][j]);
        }
        __syncthreads();
    }

    #pragma unroll
    for (int i = 0; i < 4; i++) {
        float ks = g_Ksum[b * DD + tm + i];
        #pragma unroll
        for (int j = 0; j < 4; j++) {
            int c = c0 + tc + j;
            g_KV[((size_t)b * DD + tm + i) * CC + c] = acc[i][j] + bv[c] * ks;
        }
    }
}

// ---------------------------------------------------------------------------
// K4: out[b][c][n] = x[b][c][n] + gamma * norm[b][n] * sum_d Qf[b][d][n]*KV[b][d][c]
//     norm[b][n]   = 1 / sum_d Qf[b][d][n] * (Ksum[b][d] + EPS)
// Tile: c-tile 64, n-tile 128, K=64 (single pass). grid (NN/128, CC/64, BB).
// Dynamic smem: Qs 64x128 + KVs 64x64 + ksum 64 + norm 128 = 49,920 B.
// ---------------------------------------------------------------------------
__global__ __launch_bounds__(256) void k4_out(
    const float* __restrict__ x, const float* __restrict__ gamma,
    float* __restrict__ out)
{
    extern __shared__ float sm[];
    float* Qs    = sm;                       // [64][128]
    float* KVs   = sm + 64 * 128;            // [64][64]
    float* ksumS = KVs + 64 * 64;            // [64]
    float* normS = ksumS + 64;               // [128]

    const int n0 = blockIdx.x * 128, c0 = blockIdx.y * 64, b = blockIdx.z;
    const int tid = threadIdx.x;

    const float* qf = g_Qf + (size_t)b * DD * NN;
    const float* kv = g_KV + (size_t)b * DD * CC;

    // Qs: 64x128 floats = 2048 float4 (8/thread)
    #pragma unroll
    for (int r = 0; r < 8; r++) {
        int idx = tid + r * 256;
        int d = idx >> 5, n4 = idx & 31;
        *(float4*)&Qs[d * 128 + n4 * 4] =
            *(const float4*)(qf + (size_t)d * NN + n0 + n4 * 4);
    }
    // KVs: 64x64 floats = 1024 float4 (4/thread)
    #pragma unroll
    for (int r = 0; r < 4; r++) {
        int idx = tid + r * 256;
        int d = idx >> 4, c4 = idx & 15;
        *(float4*)&KVs[d * 64 + c4 * 4] =
            *(const float4*)(kv + (size_t)d * CC + c0 + c4 * 4);
    }
    if (tid < 64) ksumS[tid] = g_Ksum[b * DD + tid] + 1e-10f;
    __syncthreads();

    if (tid < 128) {
        float s = 0.f;
        #pragma unroll
        for (int d = 0; d < 64; d++) s = fmaf(Qs[d * 128 + tid], ksumS[d], s);
        normS[tid] = 1.0f / s;
    }
    __syncthreads();

    const int tc = (tid / 16) * 4;    // 0..60
    const int tn = (tid % 16) * 8;    // 0..120
    float acc[4][8];
    #pragma unroll
    for (int i = 0; i < 4; i++)
        #pragma unroll
        for (int j = 0; j < 8; j++) acc[i][j] = 0.f;

    #pragma unroll
    for (int d = 0; d < 64; d++) {
        float a[4], q[8];
        *(float4*)a     = *(float4*)&KVs[d * 64 + tc];
        *(float4*)&q[0] = *(float4*)&Qs[d * 128 + tn];
        *(float4*)&q[4] = *(float4*)&Qs[d * 128 + tn + 4];
        #pragma unroll
        for (int i = 0; i < 4; i++)
            #pragma unroll
            for (int j = 0; j < 8; j++)
                acc[i][j] = fmaf(a[i], q[j], acc[i][j]);
    }

    const float g = gamma[0];
    const float* xb = x   + ((size_t)b * CC + c0) * NN + n0;
    float*       ob = out + ((size_t)b * CC + c0) * NN + n0;
    #pragma unroll
    for (int i = 0; i < 4; i++) {
        const int c = tc + i;
        #pragma unroll
        for (int j = 0; j < 8; j++) {
            const int n = tn + j;
            ob[(size_t)c * NN + n] =
                xb[(size_t)c * NN + n] + g * normS[n] * acc[i][j];
        }
    }
}

// ---------------------------------------------------------------------------
extern "C" void kernel_launch(void* const* d_in, const int* in_sizes, int n_in,
                              void* d_out, int out_size)
{
    const float* x     = (const float*)d_in[0];
    const float* wq    = (const float*)d_in[1];
    const float* bq    = (const float*)d_in[2];
    const float* wk    = (const float*)d_in[3];
    const float* bk    = (const float*)d_in[4];
    const float* wv    = (const float*)d_in[5];
    const float* bv    = (const float*)d_in[6];
    const float* gamma = (const float*)d_in[7];
    float* out = (float*)d_out;

    (void)in_sizes; (void)n_in; (void)out_size;

    // Idempotent non-stream attribute set (K4 needs 49,920 B dynamic smem).
    cudaFuncSetAttribute(k4_out, cudaFuncAttributeMaxDynamicSharedMemorySize, 49920);

    k1_qk <<<dim3(NN / 128, BB),        256>>>(x, wq, bq, wk, bk);
    k_ksum<<<dim3(DD, BB),              256>>>();
    k2_kx <<<dim3(CC / 64, BB, 2),      256>>>(x);
    k3_kv <<<dim3(CC / 64, BB),         256>>>(wv, bv);
    k4_out<<<dim3(NN / 128, CC / 64, BB), 256, 49920>>>(x, gamma, out);
}

// round 2
// speedup vs baseline: 1.4271x; 1.4271x over previous
#include <cuda_runtime.h>

#define BB 8
#define CC 512
#define DD 64
#define NN 4096
#define KSPLIT 4

// Scratch (device globals; allocation-free per harness rules). ~21 MB.
__device__ float g_Qf[BB * DD * NN];            // delu(Q)
__device__ float g_Kf[BB * DD * NN];            // delu(K)
__device__ float g_Ksum[BB * DD];               // row sums of Kf
__device__ float g_KXp[KSPLIT * BB * DD * CC];  // split-K partials of Kf @ X^T
__device__ float g_KV[BB * DD * CC];            // KV = KX @ wv^T + bv (x) Ksum

__device__ __forceinline__ float delu_f(float v) {
    return v > 0.f ? fmaf(10.f, v, 1.f) : __expf(10.f * v);
}
__device__ __forceinline__ float tf32_rna(float f) {
    unsigned u;
    asm("cvt.rna.tf32.f32 %0, %1;" : "=r"(u) : "f"(f));
    return __uint_as_float(u);
}
// m16n8k8 tf32 mma, acc in-place. A row-major, B col-major.
__device__ __forceinline__ void mma8(float c[4], float a0, float a1, float a2, float a3,
                                     float b0, float b1) {
    unsigned A0 = __float_as_uint(a0), A1 = __float_as_uint(a1);
    unsigned A2 = __float_as_uint(a2), A3 = __float_as_uint(a3);
    unsigned B0 = __float_as_uint(b0), B1 = __float_as_uint(b1);
    asm volatile(
        "mma.sync.aligned.m16n8k8.row.col.f32.tf32.tf32.f32 "
        "{%0,%1,%2,%3}, {%4,%5,%6,%7}, {%8,%9}, {%0,%1,%2,%3};"
        : "+f"(c[0]), "+f"(c[1]), "+f"(c[2]), "+f"(c[3])
        : "r"(A0), "r"(A1), "r"(A2), "r"(A3), "r"(B0), "r"(B1));
}

// ---------------------------------------------------------------------------
// K1 (3xTF32): [wq or wk](64x512) @ X(512x4096) + bias -> delu -> g_Qf/g_Kf
// Block 64x128, Kchunk=16, 8 warps (2x4), warp 32x32. grid (32, 2, 8).
// ---------------------------------------------------------------------------
__global__ __launch_bounds__(256) void k1_qk(
    const float* __restrict__ x,  const float* __restrict__ wq,
    const float* __restrict__ bq, const float* __restrict__ wk,
    const float* __restrict__ bk)
{
    const int b = blockIdx.z, qk = blockIdx.y;
    const int n0 = blockIdx.x * 128;
    __shared__ float Ah[64][20], Al[64][20];     // stride 20 (== 20 mod 32, A-frag ok)
    __shared__ float Bh[16][136], Bl[16][136];   // stride 136 (== 8 mod 32, B-frag ok)
    const int tid = threadIdx.x, wid = tid >> 5, lane = tid & 31;
    const int lrow = lane >> 2, lcol = lane & 3;
    const int m0w = (wid >> 2) * 32, n0w = (wid & 3) * 32;

    float acc[2][4][4];
    #pragma unroll
    for (int i = 0; i < 2; i++)
        #pragma unroll
        for (int j = 0; j < 4; j++)
            #pragma unroll
            for (int u = 0; u < 4; u++) acc[i][j][u] = 0.f;

    const float* W  = qk ? wk : wq;
    const float* xb = x + (size_t)b * CC * NN;
    const int am = tid >> 2, ac4 = (tid & 3) * 4;

    for (int k0 = 0; k0 < CC; k0 += 16) {
        // A tile 64x16 (1 float4/thread), split into hi/lo tf32
        {
            float4 v = *(const float4*)(W + (size_t)am * CC + k0 + ac4);
            const float* vp = (const float*)&v;
            #pragma unroll
            for (int u = 0; u < 4; u++) {
                float h = tf32_rna(vp[u]);
                Ah[am][ac4 + u] = h;
                Al[am][ac4 + u] = tf32_rna(vp[u] - h);
            }
        }
        // B tile 16x128 (2 float4/thread)
        #pragma unroll
        for (int r = 0; r < 2; r++) {
            int idx = tid + r * 256;
            int kk = idx >> 5, n4 = (idx & 31) * 4;
            float4 v = *(const float4*)(xb + (size_t)(k0 + kk) * NN + n0 + n4);
            const float* vp = (const float*)&v;
            #pragma unroll
            for (int u = 0; u < 4; u++) {
                float h = tf32_rna(vp[u]);
                Bh[kk][n4 + u] = h;
                Bl[kk][n4 + u] = tf32_rna(vp[u] - h);
            }
        }
        __syncthreads();
        #pragma unroll
        for (int s = 0; s < 2; s++) {
            float ah[2][4], al[2][4], bh[4][2], bl[4][2];
            #pragma unroll
            for (int i = 0; i < 2; i++) {
                int r0 = m0w + 16 * i + lrow, c0 = 8 * s + lcol;
                ah[i][0] = Ah[r0][c0];     ah[i][1] = Ah[r0 + 8][c0];
                ah[i][2] = Ah[r0][c0 + 4]; ah[i][3] = Ah[r0 + 8][c0 + 4];
                al[i][0] = Al[r0][c0];     al[i][1] = Al[r0 + 8][c0];
                al[i][2] = Al[r0][c0 + 4]; al[i][3] = Al[r0 + 8][c0 + 4];
            }
            #pragma unroll
            for (int j = 0; j < 4; j++) {
                int cn = n0w + 8 * j + lrow, kr = 8 * s + lcol;
                bh[j][0] = Bh[kr][cn]; bh[j][1] = Bh[kr + 4][cn];
                bl[j][0] = Bl[kr][cn]; bl[j][1] = Bl[kr + 4][cn];
            }
            #pragma unroll
            for (int i = 0; i < 2; i++)
                #pragma unroll
                for (int j = 0; j < 4; j++) {
                    mma8(acc[i][j], al[i][0], al[i][1], al[i][2], al[i][3], bh[j][0], bh[j][1]);
                    mma8(acc[i][j], ah[i][0], ah[i][1], ah[i][2], ah[i][3], bl[j][0], bl[j][1]);
                    mma8(acc[i][j], ah[i][0], ah[i][1], ah[i][2], ah[i][3], bh[j][0], bh[j][1]);
                }
        }
        __syncthreads();
    }

    const float* bias = qk ? bk : bq;
    float* dst = (qk ? g_Kf : g_Qf) + (size_t)b * DD * NN;
    #pragma unroll
    for (int i = 0; i < 2; i++) {
        int m = m0w + 16 * i + lrow;
        float bi0 = bias[m], bi1 = bias[m + 8];
        #pragma unroll
        for (int j = 0; j < 4; j++) {
            int n = n0 + n0w + 8 * j + 2 * lcol;
            float2 v0 = { delu_f(acc[i][j][0] + bi0), delu_f(acc[i][j][1] + bi0) };
            *(float2*)(dst + (size_t)m * NN + n) = v0;
            float2 v1 = { delu_f(acc[i][j][2] + bi1), delu_f(acc[i][j][3] + bi1) };
            *(float2*)(dst + (size_t)(m + 8) * NN + n) = v1;
        }
    }
}

// ---------------------------------------------------------------------------
// Ksum: g_Ksum[b][m] = sum_n g_Kf[b][m][n].  grid (DD, BB), 256 thr.
// ---------------------------------------------------------------------------
__global__ __launch_bounds__(256) void k_ksum()
{
    const int m = blockIdx.x, b = blockIdx.y;
    const float* src = g_Kf + ((size_t)b * DD + m) * NN;
    float s = 0.f;
    for (int i = threadIdx.x; i < NN; i += 256) s += src[i];
    __shared__ float red[256];
    red[threadIdx.x] = s;
    __syncthreads();
    for (int off = 128; off > 0; off >>= 1) {
        if (threadIdx.x < off) red[threadIdx.x] += red[threadIdx.x + off];
        __syncthreads();
    }
    if (threadIdx.x == 0) g_Ksum[b * DD + m] = red[0];
}

// ---------------------------------------------------------------------------
// K2 (tf32): KXp[s][b][d][e] = sum_{n in split} Kf[d][n]*x[e][n]
// Block 64x128(e), Kchunk=32, grid (CC/128=4, BB, KSPLIT).
// ---------------------------------------------------------------------------
__global__ __launch_bounds__(256) void k2_kx(const float* __restrict__ x)
{
    const int e0 = blockIdx.x * 128, b = blockIdx.y, sp = blockIdx.z;
    const int nbase = sp * (NN / KSPLIT);
    __shared__ float As[64][36];    // Kf[d][k], natural
    __shared__ float Bs[128][36];   // x[e][k], natural; B-frag reads [e][k] (4*lrow+lcol ok)
    const int tid = threadIdx.x, wid = tid >> 5, lane = tid & 31;
    const int lrow = lane >> 2, lcol = lane & 3;
    const int m0w = (wid >> 2) * 32, e0w = (wid & 3) * 32;

    float acc[2][4][4];
    #pragma unroll
    for (int i = 0; i < 2; i++)
        #pragma unroll
        for (int j = 0; j < 4; j++)
            #pragma unroll
            for (int u = 0; u < 4; u++) acc[i][j][u] = 0.f;

    const float* kf = g_Kf + (size_t)b * DD * NN;
    const float* xb = x + (size_t)b * CC * NN;

    for (int k0 = 0; k0 < NN / KSPLIT; k0 += 32) {
        #pragma unroll
        for (int r = 0; r < 2; r++) {
            int idx = tid + r * 256;
            int m = idx >> 3, c4 = (idx & 7) * 4;
            float4 v = *(const float4*)(kf + (size_t)m * NN + nbase + k0 + c4);
            const float* vp = (const float*)&v;
            #pragma unroll
            for (int u = 0; u < 4; u++) As[m][c4 + u] = tf32_rna(vp[u]);
        }
        #pragma unroll
        for (int r = 0; r < 4; r++) {
            int idx = tid + r * 256;
            int e = idx >> 3, c4 = (idx & 7) * 4;
            float4 v = *(const float4*)(xb + (size_t)(e0 + e) * NN + nbase + k0 + c4);
            const float* vp = (const float*)&v;
            #pragma unroll
            for (int u = 0; u < 4; u++) Bs[e][c4 + u] = tf32_rna(vp[u]);
        }
        __syncthreads();
        #pragma unroll
        for (int s = 0; s < 4; s++) {
            float a[2][4], bb[4][2];
            #pragma unroll
            for (int i = 0; i < 2; i++) {
                int r0 = m0w + 16 * i + lrow, c0 = 8 * s + lcol;
                a[i][0] = As[r0][c0];     a[i][1] = As[r0 + 8][c0];
                a[i][2] = As[r0][c0 + 4]; a[i][3] = As[r0 + 8][c0 + 4];
            }
            #pragma unroll
            for (int j = 0; j < 4; j++) {
                int er = e0w + 8 * j + lrow;
                bb[j][0] = Bs[er][8 * s + lcol]; bb[j][1] = Bs[er][8 * s + lcol + 4];
            }
            #pragma unroll
            for (int i = 0; i < 2; i++)
                #pragma unroll
                for (int j = 0; j < 4; j++)
                    mma8(acc[i][j], a[i][0], a[i][1], a[i][2], a[i][3], bb[j][0], bb[j][1]);
        }
        __syncthreads();
    }

    float* dst = g_KXp + (size_t)(sp * BB + b) * DD * CC;
    #pragma unroll
    for (int i = 0; i < 2; i++) {
        int d = m0w + 16 * i + lrow;
        #pragma unroll
        for (int j = 0; j < 4; j++) {
            int e = e0 + e0w + 8 * j + 2 * lcol;
            float2 v0 = { acc[i][j][0], acc[i][j][1] };
            *(float2*)(dst + (size_t)d * CC + e) = v0;
            float2 v1 = { acc[i][j][2], acc[i][j][3] };
            *(float2*)(dst + (size_t)(d + 8) * CC + e) = v1;
        }
    }
}

// ---------------------------------------------------------------------------
// K3 (tf32): KV[d][c] = sum_e (sum_s KXp[s])[d][e] * wv[c][e] + bv[c]*Ksum[d]
// Block 64x128(c), Kchunk=32, grid (CC/128=4, BB).
// ---------------------------------------------------------------------------
__global__ __launch_bounds__(256) void k3_kv(
    const float* __restrict__ wv, const float* __restrict__ bv)
{
    const int c0 = blockIdx.x * 128, b = blockIdx.y;
    __shared__ float As[64][36];
    __shared__ float Bs[128][36];
    const int tid = threadIdx.x, wid = tid >> 5, lane = tid & 31;
    const int lrow = lane >> 2, lcol = lane & 3;
    const int m0w = (wid >> 2) * 32, c0w = (wid & 3) * 32;

    float acc[2][4][4];
    #pragma unroll
    for (int i = 0; i < 2; i++)
        #pragma unroll
        for (int j = 0; j < 4; j++)
            #pragma unroll
            for (int u = 0; u < 4; u++) acc[i][j][u] = 0.f;

    for (int k0 = 0; k0 < CC; k0 += 32) {
        #pragma unroll
        for (int r = 0; r < 2; r++) {
            int idx = tid + r * 256;
            int m = idx >> 3, c4 = (idx & 7) * 4;
            float vx[4] = {0.f, 0.f, 0.f, 0.f};
            #pragma unroll
            for (int sp = 0; sp < KSPLIT; sp++) {
                float4 v = *(const float4*)(g_KXp +
                    (size_t)(sp * BB + b) * DD * CC + (size_t)m * CC + k0 + c4);
                vx[0] += v.x; vx[1] += v.y; vx[2] += v.z; vx[3] += v.w;
            }
            #pragma unroll
            for (int u = 0; u < 4; u++) As[m][c4 + u] = tf32_rna(vx[u]);
        }
        #pragma unroll
        for (int r = 0; r < 4; r++) {
            int idx = tid + r * 256;
            int cr = idx >> 3, c4 = (idx & 7) * 4;
            float4 v = *(const float4*)(wv + (size_t)(c0 + cr) * CC + k0 + c4);
            const float* vp = (const float*)&v;
            #pragma unroll
            for (int u = 0; u < 4; u++) Bs[cr][c4 + u] = tf32_rna(vp[u]);
        }
        __syncthreads();
        #pragma unroll
        for (int s = 0; s < 4; s++) {
            float a[2][4], bb[4][2];
            #pragma unroll
            for (int i = 0; i < 2; i++) {
                int r0 = m0w + 16 * i + lrow, cc0 = 8 * s + lcol;
                a[i][0] = As[r0][cc0];     a[i][1] = As[r0 + 8][cc0];
                a[i][2] = As[r0][cc0 + 4]; a[i][3] = As[r0 + 8][cc0 + 4];
            }
            #pragma unroll
            for (int j = 0; j < 4; j++) {
                int cr = c0w + 8 * j + lrow;
                bb[j][0] = Bs[cr][8 * s + lcol]; bb[j][1] = Bs[cr][8 * s + lcol + 4];
            }
            #pragma unroll
            for (int i = 0; i < 2; i++)
                #pragma unroll
                for (int j = 0; j < 4; j++)
                    mma8(acc[i][j], a[i][0], a[i][1], a[i][2], a[i][3], bb[j][0], bb[j][1]);
        }
        __syncthreads();
    }

    #pragma unroll
    for (int i = 0; i < 2; i++) {
        int d = m0w + 16 * i + lrow;
        float ks0 = g_Ksum[b * DD + d], ks1 = g_Ksum[b * DD + d + 8];
        #pragma unroll
        for (int j = 0; j < 4; j++) {
            int c = c0 + c0w + 8 * j + 2 * lcol;
            float bv0 = bv[c], bv1 = bv[c + 1];
            float2 v0 = { acc[i][j][0] + bv0 * ks0, acc[i][j][1] + bv1 * ks0 };
            *(float2*)(g_KV + ((size_t)b * DD + d) * CC + c) = v0;
            float2 v1 = { acc[i][j][2] + bv0 * ks1, acc[i][j][3] + bv1 * ks1 };
            *(float2*)(g_KV + ((size_t)b * DD + d + 8) * CC + c) = v1;
        }
    }
}

// ---------------------------------------------------------------------------
// K4 (tf32): out[c][n] = x[c][n] + gamma * norm[n] * sum_d KV[d][c]*Qf[d][n]
// Block: c-tile 64 (M), n-tile 128 (N), K=64. grid (32, 8, 8).
// As=KV[d][c] stride 72; Bs=Qf[d][n] stride 136. 54,016 B dynamic smem.
// ---------------------------------------------------------------------------
__global__ __launch_bounds__(256) void k4_out(
    const float* __restrict__ x, const float* __restrict__ gamma,
    float* __restrict__ out)
{
    extern __shared__ float sm[];
    float (*As)[72]  = (float(*)[72])sm;               // [64][72]
    float (*Bs)[136] = (float(*)[136])(sm + 64 * 72);  // [64][136]
    float* ksumS = sm + 64 * 72 + 64 * 136;            // [64]
    float* normS = ksumS + 64;                          // [128]

    const int n0 = blockIdx.x * 128, c0 = blockIdx.y * 64, b = blockIdx.z;
    const int tid = threadIdx.x, wid = tid >> 5, lane = tid & 31;
    const int lrow = lane >> 2, lcol = lane & 3;
    const int m0w = (wid >> 2) * 32, n0w = (wid & 3) * 32;

    #pragma unroll
    for (int r = 0; r < 8; r++) {
        int idx = tid + r * 256;
        int d = idx >> 5, n4 = (idx & 31) * 4;
        float4 v = *(const float4*)(g_Qf + ((size_t)b * DD + d) * NN + n0 + n4);
        const float* vp = (const float*)&v;
        #pragma unroll
        for (int u = 0; u < 4; u++) Bs[d][n4 + u] = tf32_rna(vp[u]);
    }
    #pragma unroll
    for (int r = 0; r < 4; r++) {
        int idx = tid + r * 256;
        int d = idx >> 4, c4 = (idx & 15) * 4;
        float4 v = *(const float4*)(g_KV + ((size_t)b * DD + d) * CC + c0 + c4);
        const float* vp = (const float*)&v;
        #pragma unroll
        for (int u = 0; u < 4; u++) As[d][c4 + u] = tf32_rna(vp[u]);
    }
    if (tid < 64) ksumS[tid] = g_Ksum[b * DD + tid] + 1e-10f;
    __syncthreads();

    if (tid < 128) {
        float s = 0.f;
        #pragma unroll
        for (int d = 0; d < 64; d++) s = fmaf(Bs[d][tid], ksumS[d], s);
        normS[tid] = 1.0f / s;
    }
    __syncthreads();

    float acc[2][4][4];
    #pragma unroll
    for (int i = 0; i < 2; i++)
        #pragma unroll
        for (int j = 0; j < 4; j++)
            #pragma unroll
            for (int u = 0; u < 4; u++) acc[i][j][u] = 0.f;

    #pragma unroll
    for (int s = 0; s < 8; s++) {
        float a[2][4], bb[4][2];
        #pragma unroll
        for (int i = 0; i < 2; i++) {
            int cm = m0w + 16 * i + lrow, kb = 8 * s + lcol;
            a[i][0] = As[kb][cm];     a[i][1] = As[kb][cm + 8];
            a[i][2] = As[kb + 4][cm]; a[i][3] = As[kb + 4][cm + 8];
        }
        #pragma unroll
        for (int j = 0; j < 4; j++) {
            int nc = n0w + 8 * j + lrow;
            bb[j][0] = Bs[8 * s + lcol][nc]; bb[j][1] = Bs[8 * s + lcol + 4][nc];
        }
        #pragma unroll
        for (int i = 0; i < 2; i++)
            #pragma unroll
            for (int j = 0; j < 4; j++)
                mma8(acc[i][j], a[i][0], a[i][1], a[i][2], a[i][3], bb[j][0], bb[j][1]);
    }

    const float g = gamma[0];
    #pragma unroll
    for (int i = 0; i < 2; i++) {
        int c = c0 + m0w + 16 * i + lrow;
        #pragma unroll
        for (int j = 0; j < 4; j++) {
            int nl = n0w + 8 * j + 2 * lcol;
            int n = n0 + nl;
            float2 nr = *(float2*)&normS[nl];
            const float* xp0 = x + ((size_t)b * CC + c) * NN + n;
            float*       op0 = out + ((size_t)b * CC + c) * NN + n;
            float2 xv0 = *(const float2*)xp0;
            float2 o0 = { xv0.x + g * nr.x * acc[i][j][0],
                          xv0.y + g * nr.y * acc[i][j][1] };
            *(float2*)op0 = o0;
            const float* xp1 = x + ((size_t)b * CC + c + 8) * NN + n;
            float*       op1 = out + ((size_t)b * CC + c + 8) * NN + n;
            float2 xv1 = *(const float2*)xp1;
            float2 o1 = { xv1.x + g * nr.x * acc[i][j][2],
                          xv1.y + g * nr.y * acc[i][j][3] };
            *(float2*)op1 = o1;
        }
    }
}

// ---------------------------------------------------------------------------
extern "C" void kernel_launch(void* const* d_in, const int* in_sizes, int n_in,
                              void* d_out, int out_size)
{
    const float* x     = (const float*)d_in[0];
    const float* wq    = (const float*)d_in[1];
    const float* bq    = (const float*)d_in[2];
    const float* wk    = (const float*)d_in[3];
    const float* bk    = (const float*)d_in[4];
    const float* wv    = (const float*)d_in[5];
    const float* bv    = (const float*)d_in[6];
    const float* gamma = (const float*)d_in[7];
    float* out = (float*)d_out;

    (void)in_sizes; (void)n_in; (void)out_size;

    cudaFuncSetAttribute(k4_out, cudaFuncAttributeMaxDynamicSharedMemorySize, 54016);

    k1_qk <<<dim3(NN / 128, 2, BB),          256>>>(x, wq, bq, wk, bk);
    k_ksum<<<dim3(DD, BB),                   256>>>();
    k2_kx <<<dim3(CC / 128, BB, KSPLIT),     256>>>(x);
    k3_kv <<<dim3(CC / 128, BB),             256>>>(wv, bv);
    k4_out<<<dim3(NN / 128, CC / 64, BB),    256, 54016>>>(x, gamma, out);
}

// round 3
// speedup vs baseline: 1.8056x; 1.2652x over previous
#include <cuda_runtime.h>

#define BB 8
#define CC 512
#define DD 64
#define NN 4096
#define KSPLIT 8      // k2 split-K over n
#define ESPLIT 4      // k3 split over e

// Scratch (device globals). ~30 MB.
__device__ float g_Qf[BB * DD * NN];             // delu(Q)  8 MB
__device__ float g_Kf[BB * DD * NN];             // delu(K)  8 MB
__device__ float g_Ksum[BB * DD];
__device__ float g_KXp[KSPLIT * BB * DD * CC];   // 8 MB split-K partials of Kf@X^T
__device__ float g_KX[BB * DD * CC];             // 1 MB summed
__device__ float g_KVp[ESPLIT * BB * DD * CC];   // 4 MB partials of KX@wv^T

__device__ __forceinline__ float delu_f(float v) {
    return v > 0.f ? fmaf(10.f, v, 1.f) : __expf(10.f * v);
}
__device__ __forceinline__ float tf32_rna(float f) {
    unsigned u;
    asm("cvt.rna.tf32.f32 %0, %1;" : "=r"(u) : "f"(f));
    return __uint_as_float(u);
}
__device__ __forceinline__ void mma8(float c[4], float a0, float a1, float a2, float a3,
                                     float b0, float b1) {
    unsigned A0 = __float_as_uint(a0), A1 = __float_as_uint(a1);
    unsigned A2 = __float_as_uint(a2), A3 = __float_as_uint(a3);
    unsigned B0 = __float_as_uint(b0), B1 = __float_as_uint(b1);
    asm volatile(
        "mma.sync.aligned.m16n8k8.row.col.f32.tf32.tf32.f32 "
        "{%0,%1,%2,%3}, {%4,%5,%6,%7}, {%8,%9}, {%0,%1,%2,%3};"
        : "+f"(c[0]), "+f"(c[1]), "+f"(c[2]), "+f"(c[3])
        : "r"(A0), "r"(A1), "r"(A2), "r"(A3), "r"(B0), "r"(B1));
}

// ---------------------------------------------------------------------------
// K1 (3xTF32, fused Q+K): [wq;wk](128x512) @ X(512x4096) + bias -> delu
// Block 128x128, Kchunk=16, 8 warps (2Mx4N), warp 64x32. grid (32, 8).
// Register-prefetch pipelined.
// ---------------------------------------------------------------------------
__global__ __launch_bounds__(256) void k1_qk(
    const float* __restrict__ x,  const float* __restrict__ wq,
    const float* __restrict__ bq, const float* __restrict__ wk,
    const float* __restrict__ bk)
{
    const int b = blockIdx.y;
    const int n0 = blockIdx.x * 128;
    __shared__ float Ah[128][20], Al[128][20];
    __shared__ float Bh[16][136], Bl[16][136];
    const int tid = threadIdx.x, wid = tid >> 5, lane = tid & 31;
    const int lrow = lane >> 2, lcol = lane & 3;
    const int m0w = (wid >> 2) * 64, n0w = (wid & 3) * 32;

    float acc[4][4][4];
    #pragma unroll
    for (int i = 0; i < 4; i++)
        #pragma unroll
        for (int j = 0; j < 4; j++)
            #pragma unroll
            for (int u = 0; u < 4; u++) acc[i][j][u] = 0.f;

    const float* xb = x + (size_t)b * CC * NN;
    const int am = tid >> 2, ac4 = (tid & 3) * 4;      // A: rows am / am+64
    const int bkk = tid >> 5, bn4 = (tid & 31) * 4;    // B: rows bkk / bkk+8

    float4 pa0, pa1, pb0, pb1;
    auto ldTiles = [&](int k0) {
        pa0 = *(const float4*)(wq + (size_t)am * CC + k0 + ac4);
        pa1 = *(const float4*)(wk + (size_t)am * CC + k0 + ac4);
        pb0 = *(const float4*)(xb + (size_t)(k0 + bkk) * NN + n0 + bn4);
        pb1 = *(const float4*)(xb + (size_t)(k0 + 8 + bkk) * NN + n0 + bn4);
    };
    auto stTiles = [&]() {
        const float* p0 = (const float*)&pa0;
        const float* p1 = (const float*)&pa1;
        #pragma unroll
        for (int u = 0; u < 4; u++) {
            float h0 = tf32_rna(p0[u]);
            Ah[am][ac4 + u] = h0;  Al[am][ac4 + u] = tf32_rna(p0[u] - h0);
            float h1 = tf32_rna(p1[u]);
            Ah[am + 64][ac4 + u] = h1;  Al[am + 64][ac4 + u] = tf32_rna(p1[u] - h1);
        }
        const float* q0 = (const float*)&pb0;
        const float* q1 = (const float*)&pb1;
        #pragma unroll
        for (int u = 0; u < 4; u++) {
            float h0 = tf32_rna(q0[u]);
            Bh[bkk][bn4 + u] = h0;  Bl[bkk][bn4 + u] = tf32_rna(q0[u] - h0);
            float h1 = tf32_rna(q1[u]);
            Bh[bkk + 8][bn4 + u] = h1;  Bl[bkk + 8][bn4 + u] = tf32_rna(q1[u] - h1);
        }
    };

    ldTiles(0);
    stTiles();
    __syncthreads();

    for (int k0 = 0; k0 < CC; k0 += 16) {
        const bool more = (k0 + 16 < CC);
        if (more) ldTiles(k0 + 16);
        #pragma unroll
        for (int s = 0; s < 2; s++) {
            float ah[4][4], al[4][4], bh[4][2], bl[4][2];
            #pragma unroll
            for (int i = 0; i < 4; i++) {
                int r0 = m0w + 16 * i + lrow, c0 = 8 * s + lcol;
                ah[i][0] = Ah[r0][c0];     ah[i][1] = Ah[r0 + 8][c0];
                ah[i][2] = Ah[r0][c0 + 4]; ah[i][3] = Ah[r0 + 8][c0 + 4];
                al[i][0] = Al[r0][c0];     al[i][1] = Al[r0 + 8][c0];
                al[i][2] = Al[r0][c0 + 4]; al[i][3] = Al[r0 + 8][c0 + 4];
            }
            #pragma unroll
            for (int j = 0; j < 4; j++) {
                int cn = n0w + 8 * j + lrow, kr = 8 * s + lcol;
                bh[j][0] = Bh[kr][cn]; bh[j][1] = Bh[kr + 4][cn];
                bl[j][0] = Bl[kr][cn]; bl[j][1] = Bl[kr + 4][cn];
            }
            #pragma unroll
            for (int i = 0; i < 4; i++)
                #pragma unroll
                for (int j = 0; j < 4; j++) {
                    mma8(acc[i][j], al[i][0], al[i][1], al[i][2], al[i][3], bh[j][0], bh[j][1]);
                    mma8(acc[i][j], ah[i][0], ah[i][1], ah[i][2], ah[i][3], bl[j][0], bl[j][1]);
                    mma8(acc[i][j], ah[i][0], ah[i][1], ah[i][2], ah[i][3], bh[j][0], bh[j][1]);
                }
        }
        __syncthreads();
        if (more) {
            stTiles();
            __syncthreads();
        }
    }

    #pragma unroll
    for (int i = 0; i < 4; i++) {
        int m = m0w + 16 * i + lrow;   // 0..127; 16-row tiles never straddle 64
        const bool isK = (m >= 64);
        int mm = isK ? m - 64 : m;
        float bi0 = isK ? bk[mm] : bq[mm];
        float bi1 = isK ? bk[mm + 8] : bq[mm + 8];
        float* dst = (isK ? g_Kf : g_Qf) + (size_t)b * DD * NN;
        #pragma unroll
        for (int j = 0; j < 4; j++) {
            int n = n0 + n0w + 8 * j + 2 * lcol;
            float2 v0 = { delu_f(acc[i][j][0] + bi0), delu_f(acc[i][j][1] + bi0) };
            *(float2*)(dst + (size_t)mm * NN + n) = v0;
            float2 v1 = { delu_f(acc[i][j][2] + bi1), delu_f(acc[i][j][3] + bi1) };
            *(float2*)(dst + (size_t)(mm + 8) * NN + n) = v1;
        }
    }
}

// ---------------------------------------------------------------------------
// Ksum: g_Ksum[b][m] = sum_n g_Kf[b][m][n].  grid (DD, BB), 256 thr.
// ---------------------------------------------------------------------------
__global__ __launch_bounds__(256) void k_ksum()
{
    const int m = blockIdx.x, b = blockIdx.y;
    const float* src = g_Kf + ((size_t)b * DD + m) * NN;
    float s = 0.f;
    for (int i = threadIdx.x; i < NN / 4; i += 256) {
        float4 v = ((const float4*)src)[i];
        s += (v.x + v.y) + (v.z + v.w);
    }
    __shared__ float red[256];
    red[threadIdx.x] = s;
    __syncthreads();
    for (int off = 128; off > 0; off >>= 1) {
        if (threadIdx.x < off) red[threadIdx.x] += red[threadIdx.x + off];
        __syncthreads();
    }
    if (threadIdx.x == 0) g_Ksum[b * DD + m] = red[0];
}

// ---------------------------------------------------------------------------
// K2 (tf32): KXp[s][b][d][e] = sum_{n in split} Kf[d][n]*x[e][n]
// Block 64x128(e), Kchunk=32, K=512 per split. grid (4, 8, KSPLIT=8) = 256.
// Register-prefetch pipelined.
// ---------------------------------------------------------------------------
__global__ __launch_bounds__(256) void k2_kx(const float* __restrict__ x)
{
    const int e0 = blockIdx.x * 128, b = blockIdx.y, sp = blockIdx.z;
    const int nbase = sp * (NN / KSPLIT);
    __shared__ float As[64][36];
    __shared__ float Bs[128][36];
    const int tid = threadIdx.x, wid = tid >> 5, lane = tid & 31;
    const int lrow = lane >> 2, lcol = lane & 3;
    const int m0w = (wid >> 2) * 32, e0w = (wid & 3) * 32;

    float acc[2][4][4];
    #pragma unroll
    for (int i = 0; i < 2; i++)
        #pragma unroll
        for (int j = 0; j < 4; j++)
            #pragma unroll
            for (int u = 0; u < 4; u++) acc[i][j][u] = 0.f;

    const float* kf = g_Kf + (size_t)b * DD * NN + nbase;
    const float* xb = x + (size_t)b * CC * NN + nbase;
    const int arow = tid >> 3, ac4 = (tid & 7) * 4;    // A rows arow/arow+32
    const int brow = tid >> 3;                          // B rows brow/+32/+64/+96

    float4 pa[2], pb[4];
    auto ldTiles = [&](int k0) {
        pa[0] = *(const float4*)(kf + (size_t)arow * NN + k0 + ac4);
        pa[1] = *(const float4*)(kf + (size_t)(arow + 32) * NN + k0 + ac4);
        #pragma unroll
        for (int r = 0; r < 4; r++)
            pb[r] = *(const float4*)(xb + (size_t)(e0 + brow + 32 * r) * NN + k0 + ac4);
    };
    auto stTiles = [&]() {
        #pragma unroll
        for (int u = 0; u < 4; u++) {
            As[arow][ac4 + u]      = tf32_rna(((const float*)&pa[0])[u]);
            As[arow + 32][ac4 + u] = tf32_rna(((const float*)&pa[1])[u]);
        }
        #pragma unroll
        for (int r = 0; r < 4; r++)
            #pragma unroll
            for (int u = 0; u < 4; u++)
                Bs[brow + 32 * r][ac4 + u] = tf32_rna(((const float*)&pb[r])[u]);
    };

    ldTiles(0);
    stTiles();
    __syncthreads();

    for (int k0 = 0; k0 < NN / KSPLIT; k0 += 32) {
        const bool more = (k0 + 32 < NN / KSPLIT);
        if (more) ldTiles(k0 + 32);
        #pragma unroll
        for (int s = 0; s < 4; s++) {
            float a[2][4], bb[4][2];
            #pragma unroll
            for (int i = 0; i < 2; i++) {
                int r0 = m0w + 16 * i + lrow, c0 = 8 * s + lcol;
                a[i][0] = As[r0][c0];     a[i][1] = As[r0 + 8][c0];
                a[i][2] = As[r0][c0 + 4]; a[i][3] = As[r0 + 8][c0 + 4];
            }
            #pragma unroll
            for (int j = 0; j < 4; j++) {
                int er = e0w + 8 * j + lrow;
                bb[j][0] = Bs[er][8 * s + lcol]; bb[j][1] = Bs[er][8 * s + lcol + 4];
            }
            #pragma unroll
            for (int i = 0; i < 2; i++)
                #pragma unroll
                for (int j = 0; j < 4; j++)
                    mma8(acc[i][j], a[i][0], a[i][1], a[i][2], a[i][3], bb[j][0], bb[j][1]);
        }
        __syncthreads();
        if (more) {
            stTiles();
            __syncthreads();
        }
    }

    float* dst = g_KXp + (size_t)(sp * BB + b) * DD * CC;
    #pragma unroll
    for (int i = 0; i < 2; i++) {
        int d = m0w + 16 * i + lrow;
        #pragma unroll
        for (int j = 0; j < 4; j++) {
            int e = e0 + e0w + 8 * j + 2 * lcol;
            float2 v0 = { acc[i][j][0], acc[i][j][1] };
            *(float2*)(dst + (size_t)d * CC + e) = v0;
            float2 v1 = { acc[i][j][2], acc[i][j][3] };
            *(float2*)(dst + (size_t)(d + 8) * CC + e) = v1;
        }
    }
}

// ---------------------------------------------------------------------------
// sumKX: g_KX = sum over KSPLIT of g_KXp. 65536 float4. grid 256, 256 thr.
// ---------------------------------------------------------------------------
__global__ __launch_bounds__(256) void k_sumkx()
{
    const int i = blockIdx.x * 256 + threadIdx.x;
    const int stride = BB * DD * CC / 4;
    const float4* p = (const float4*)g_KXp;
    float4 s = p[i];
    #pragma unroll
    for (int sp = 1; sp < KSPLIT; sp++) {
        float4 v = p[(size_t)sp * stride + i];
        s.x += v.x; s.y += v.y; s.z += v.z; s.w += v.w;
    }
    ((float4*)g_KX)[i] = s;
}

// ---------------------------------------------------------------------------
// K3 (tf32): KVp[sp][b][d][c] = sum_{e in 128-split} KX[d][e]*wv[c][e]
// Block 64x128(c), K=128 (4 chunks). grid (4, 8, ESPLIT=4) = 128.
// ---------------------------------------------------------------------------
__global__ __launch_bounds__(256) void k3_kv(const float* __restrict__ wv)
{
    const int c0 = blockIdx.x * 128, b = blockIdx.y, sp = blockIdx.z;
    const int ebase = sp * (CC / ESPLIT);
    __shared__ float As[64][36];
    __shared__ float Bs[128][36];
    const int tid = threadIdx.x, wid = tid >> 5, lane = tid & 31;
    const int lrow = lane >> 2, lcol = lane & 3;
    const int m0w = (wid >> 2) * 32, c0w = (wid & 3) * 32;

    float acc[2][4][4];
    #pragma unroll
    for (int i = 0; i < 2; i++)
        #pragma unroll
        for (int j = 0; j < 4; j++)
            #pragma unroll
            for (int u = 0; u < 4; u++) acc[i][j][u] = 0.f;

    const float* kx = g_KX + (size_t)b * DD * CC + ebase;
    const int arow = tid >> 3, ac4 = (tid & 7) * 4;
    const int brow = tid >> 3;

    for (int k0 = 0; k0 < CC / ESPLIT; k0 += 32) {
        {
            float4 v0 = *(const float4*)(kx + (size_t)arow * CC + k0 + ac4);
            float4 v1 = *(const float4*)(kx + (size_t)(arow + 32) * CC + k0 + ac4);
            #pragma unroll
            for (int u = 0; u < 4; u++) {
                As[arow][ac4 + u]      = tf32_rna(((const float*)&v0)[u]);
                As[arow + 32][ac4 + u] = tf32_rna(((const float*)&v1)[u]);
            }
            #pragma unroll
            for (int r = 0; r < 4; r++) {
                float4 v = *(const float4*)(wv +
                    (size_t)(c0 + brow + 32 * r) * CC + ebase + k0 + ac4);
                #pragma unroll
                for (int u = 0; u < 4; u++)
                    Bs[brow + 32 * r][ac4 + u] = tf32_rna(((const float*)&v)[u]);
            }
        }
        __syncthreads();
        #pragma unroll
        for (int s = 0; s < 4; s++) {
            float a[2][4], bb[4][2];
            #pragma unroll
            for (int i = 0; i < 2; i++) {
                int r0 = m0w + 16 * i + lrow, cc0 = 8 * s + lcol;
                a[i][0] = As[r0][cc0];     a[i][1] = As[r0 + 8][cc0];
                a[i][2] = As[r0][cc0 + 4]; a[i][3] = As[r0 + 8][cc0 + 4];
            }
            #pragma unroll
            for (int j = 0; j < 4; j++) {
                int cr = c0w + 8 * j + lrow;
                bb[j][0] = Bs[cr][8 * s + lcol]; bb[j][1] = Bs[cr][8 * s + lcol + 4];
            }
            #pragma unroll
            for (int i = 0; i < 2; i++)
                #pragma unroll
                for (int j = 0; j < 4; j++)
                    mma8(acc[i][j], a[i][0], a[i][1], a[i][2], a[i][3], bb[j][0], bb[j][1]);
        }
        __syncthreads();
    }

    float* dst = g_KVp + (size_t)(sp * BB + b) * DD * CC;
    #pragma unroll
    for (int i = 0; i < 2; i++) {
        int d = m0w + 16 * i + lrow;
        #pragma unroll
        for (int j = 0; j < 4; j++) {
            int c = c0 + c0w + 8 * j + 2 * lcol;
            float2 v0 = { acc[i][j][0], acc[i][j][1] };
            *(float2*)(dst + (size_t)d * CC + c) = v0;
            float2 v1 = { acc[i][j][2], acc[i][j][3] };
            *(float2*)(dst + (size_t)(d + 8) * CC + c) = v1;
        }
    }
}

// ---------------------------------------------------------------------------
// K4 (tf32): out[c][n] = x[c][n] + gamma*norm[n]*sum_d KV[d][c]*Qf[d][n]
// KV[d][c] = sum_sp KVp[sp][d][c] + bv[c]*Ksum[d]  (folded into As build)
// Block: c-tile 128 (M), n-tile 128 (N), K=64. grid (32, 4, 8) = 1024.
// 8 warps: 4Mx2N, warp 32x64. Dynamic smem 70,400 B.
// ---------------------------------------------------------------------------
__global__ __launch_bounds__(256) void k4_out(
    const float* __restrict__ x, const float* __restrict__ bv,
    const float* __restrict__ gamma, float* __restrict__ out)
{
    extern __shared__ float sm[];
    float (*As)[136] = (float(*)[136])sm;                // [64][136]  KV[d][c]
    float (*Bs)[136] = (float(*)[136])(sm + 64 * 136);   // [64][136]  Qf[d][n]
    float* ksumS = sm + 2 * 64 * 136;                     // [64] (+eps)
    float* normS = ksumS + 64;                            // [128]

    const int n0 = blockIdx.x * 128, c0 = blockIdx.y * 128, b = blockIdx.z;
    const int tid = threadIdx.x, wid = tid >> 5, lane = tid & 31;
    const int lrow = lane >> 2, lcol = lane & 3;
    const int m0w = (wid >> 1) * 32, n0w = (wid & 1) * 64;

    // Qf tile -> Bs
    #pragma unroll
    for (int r = 0; r < 8; r++) {
        int idx = tid + r * 256;
        int d = idx >> 5, n4 = (idx & 31) * 4;
        float4 v = *(const float4*)(g_Qf + ((size_t)b * DD + d) * NN + n0 + n4);
        #pragma unroll
        for (int u = 0; u < 4; u++) Bs[d][n4 + u] = tf32_rna(((const float*)&v)[u]);
    }
    // KV tile -> As (sum ESPLIT partials + bias term)
    #pragma unroll
    for (int r = 0; r < 8; r++) {
        int idx = tid + r * 256;
        int d = idx >> 5, c4 = (idx & 31) * 4;
        float4 s = *(const float4*)(g_KVp + ((size_t)b * DD + d) * CC + c0 + c4);
        #pragma unroll
        for (int sp = 1; sp < ESPLIT; sp++) {
            float4 v = *(const float4*)(g_KVp +
                ((size_t)(sp * BB + b) * DD + d) * CC + c0 + c4);
            s.x += v.x; s.y += v.y; s.z += v.z; s.w += v.w;
        }
        float4 bvv = *(const float4*)(bv + c0 + c4);
        float ks = g_Ksum[b * DD + d];
        As[d][c4 + 0] = tf32_rna(s.x + bvv.x * ks);
        As[d][c4 + 1] = tf32_rna(s.y + bvv.y * ks);
        As[d][c4 + 2] = tf32_rna(s.z + bvv.z * ks);
        As[d][c4 + 3] = tf32_rna(s.w + bvv.w * ks);
    }
    if (tid < 64) ksumS[tid] = g_Ksum[b * DD + tid] + 1e-10f;
    __syncthreads();

    if (tid < 128) {
        float s = 0.f;
        #pragma unroll
        for (int d = 0; d < 64; d++) s = fmaf(Bs[d][tid], ksumS[d], s);
        normS[tid] = 1.0f / s;
    }
    __syncthreads();

    float acc[2][8][4];
    #pragma unroll
    for (int i = 0; i < 2; i++)
        #pragma unroll
        for (int j = 0; j < 8; j++)
            #pragma unroll
            for (int u = 0; u < 4; u++) acc[i][j][u] = 0.f;

    #pragma unroll
    for (int s = 0; s < 8; s++) {
        float a[2][4], bb[8][2];
        #pragma unroll
        for (int i = 0; i < 2; i++) {
            int cm = m0w + 16 * i + lrow, kb = 8 * s + lcol;
            a[i][0] = As[kb][cm];     a[i][1] = As[kb][cm + 8];
            a[i][2] = As[kb + 4][cm]; a[i][3] = As[kb + 4][cm + 8];
        }
        #pragma unroll
        for (int j = 0; j < 8; j++) {
            int nc = n0w + 8 * j + lrow;
            bb[j][0] = Bs[8 * s + lcol][nc]; bb[j][1] = Bs[8 * s + lcol + 4][nc];
        }
        #pragma unroll
        for (int i = 0; i < 2; i++)
            #pragma unroll
            for (int j = 0; j < 8; j++)
                mma8(acc[i][j], a[i][0], a[i][1], a[i][2], a[i][3], bb[j][0], bb[j][1]);
    }

    const float g = gamma[0];
    #pragma unroll
    for (int i = 0; i < 2; i++) {
        int c = c0 + m0w + 16 * i + lrow;
        #pragma unroll
        for (int j = 0; j < 8; j++) {
            int nl = n0w + 8 * j + 2 * lcol;
            int n = n0 + nl;
            float2 nr = *(float2*)&normS[nl];
            const float* xp0 = x + ((size_t)b * CC + c) * NN + n;
            float*       op0 = out + ((size_t)b * CC + c) * NN + n;
            float2 xv0 = *(const float2*)xp0;
            float2 o0 = { xv0.x + g * nr.x * acc[i][j][0],
                          xv0.y + g * nr.y * acc[i][j][1] };
            *(float2*)op0 = o0;
            const float* xp1 = x + ((size_t)b * CC + c + 8) * NN + n;
            float*       op1 = out + ((size_t)b * CC + c + 8) * NN + n;
            float2 xv1 = *(const float2*)xp1;
            float2 o1 = { xv1.x + g * nr.x * acc[i][j][2],
                          xv1.y + g * nr.y * acc[i][j][3] };
            *(float2*)op1 = o1;
        }
    }
}

// ---------------------------------------------------------------------------
extern "C" void kernel_launch(void* const* d_in, const int* in_sizes, int n_in,
                              void* d_out, int out_size)
{
    const float* x     = (const float*)d_in[0];
    const float* wq    = (const float*)d_in[1];
    const float* bq    = (const float*)d_in[2];
    const float* wk    = (const float*)d_in[3];
    const float* bk    = (const float*)d_in[4];
    const float* wv    = (const float*)d_in[5];
    const float* bv    = (const float*)d_in[6];
    const float* gamma = (const float*)d_in[7];
    float* out = (float*)d_out;

    (void)in_sizes; (void)n_in; (void)out_size;

    cudaFuncSetAttribute(k4_out, cudaFuncAttributeMaxDynamicSharedMemorySize, 70400);

    k1_qk  <<<dim3(NN / 128, BB),          256>>>(x, wq, bq, wk, bk);
    k_ksum <<<dim3(DD, BB),                256>>>();
    k2_kx  <<<dim3(CC / 128, BB, KSPLIT),  256>>>(x);
    k_sumkx<<<dim3(BB * DD * CC / 1024),   256>>>();
    k3_kv  <<<dim3(CC / 128, BB, ESPLIT),  256>>>(wv);
    k4_out <<<dim3(NN / 128, CC / 128, BB), 256, 70400>>>(x, bv, gamma, out);
}

// round 4
// speedup vs baseline: 2.2151x; 1.2268x over previous
#include <cuda_runtime.h>

#define BB 8
#define CC 512
#define DD 64
#define NN 4096
#define KSPLIT 8      // k2 split-K over n
#define ESPLIT 4      // k3 split over e

// Scratch (device globals). ~30 MB.
__device__ float g_Qf[BB * DD * NN];             // delu(Q)  8 MB
__device__ float g_Kf[BB * DD * NN];             // delu(K)  8 MB
__device__ float g_Ksum[BB * DD];
__device__ float g_KXp[KSPLIT * BB * DD * CC];   // split-K partials of Kf@X^T
__device__ float g_KX[BB * DD * CC];             // summed
__device__ float g_KVp[ESPLIT * BB * DD * CC];   // partials of KX@wv^T

__device__ __forceinline__ float delu_f(float v) {
    return v > 0.f ? fmaf(10.f, v, 1.f) : __expf(10.f * v);
}
__device__ __forceinline__ float tf32_rna(float f) {
    unsigned u;
    asm("cvt.rna.tf32.f32 %0, %1;" : "=r"(u) : "f"(f));
    return __uint_as_float(u);
}
__device__ __forceinline__ void mma8(float c[4], float a0, float a1, float a2, float a3,
                                     float b0, float b1) {
    unsigned A0 = __float_as_uint(a0), A1 = __float_as_uint(a1);
    unsigned A2 = __float_as_uint(a2), A3 = __float_as_uint(a3);
    unsigned B0 = __float_as_uint(b0), B1 = __float_as_uint(b1);
    asm volatile(
        "mma.sync.aligned.m16n8k8.row.col.f32.tf32.tf32.f32 "
        "{%0,%1,%2,%3}, {%4,%5,%6,%7}, {%8,%9}, {%0,%1,%2,%3};"
        : "+f"(c[0]), "+f"(c[1]), "+f"(c[2]), "+f"(c[3])
        : "r"(A0), "r"(A1), "r"(A2), "r"(A3), "r"(B0), "r"(B1));
}

// ---------------------------------------------------------------------------
// K1 (3xTF32, fused Q+K): [wq;wk](128x512) @ X(512x4096) + bias -> delu
// Block 128x128, Kchunk=16, 8 warps (2Mx4N), warp 64x32. grid (32, 8).
// Ping-pong double-buffered: ONE __syncthreads per K-iter.
// Buffer layout (floats): Ah[128][20] @0, Al @2560, Bh[16][136] @5120, Bl @7296.
// Buf = 9472 floats; 2 bufs = 75,776 B dynamic smem.
// ---------------------------------------------------------------------------
#define K1_BUF 9472
__global__ __launch_bounds__(256) void k1_qk(
    const float* __restrict__ x,  const float* __restrict__ wq,
    const float* __restrict__ bq, const float* __restrict__ wk,
    const float* __restrict__ bk)
{
    extern __shared__ float sb[];
    const int b = blockIdx.y;
    const int n0 = blockIdx.x * 128;
    const int tid = threadIdx.x, wid = tid >> 5, lane = tid & 31;
    const int lrow = lane >> 2, lcol = lane & 3;
    const int m0w = (wid >> 2) * 64, n0w = (wid & 3) * 32;

    float acc[4][4][4];
    #pragma unroll
    for (int i = 0; i < 4; i++)
        #pragma unroll
        for (int j = 0; j < 4; j++)
            #pragma unroll
            for (int u = 0; u < 4; u++) acc[i][j][u] = 0.f;

    const float* xb = x + (size_t)b * CC * NN;
    const int am = tid >> 2, ac4 = (tid & 3) * 4;
    const int bkk = tid >> 5, bn4 = (tid & 31) * 4;

    float4 pa0, pa1, pb0, pb1;
    auto ldTiles = [&](int k0) {
        pa0 = *(const float4*)(wq + (size_t)am * CC + k0 + ac4);
        pa1 = *(const float4*)(wk + (size_t)am * CC + k0 + ac4);
        pb0 = *(const float4*)(xb + (size_t)(k0 + bkk) * NN + n0 + bn4);
        pb1 = *(const float4*)(xb + (size_t)(k0 + 8 + bkk) * NN + n0 + bn4);
    };
    auto stTiles = [&](float* buf) {
        float* Ah = buf;            float* Al = buf + 2560;
        float* Bh = buf + 5120;     float* Bl = buf + 7296;
        const float* p0 = (const float*)&pa0;
        const float* p1 = (const float*)&pa1;
        #pragma unroll
        for (int u = 0; u < 4; u++) {
            float h0 = tf32_rna(p0[u]);
            Ah[am * 20 + ac4 + u] = h0;
            Al[am * 20 + ac4 + u] = tf32_rna(p0[u] - h0);
            float h1 = tf32_rna(p1[u]);
            Ah[(am + 64) * 20 + ac4 + u] = h1;
            Al[(am + 64) * 20 + ac4 + u] = tf32_rna(p1[u] - h1);
        }
        const float* q0 = (const float*)&pb0;
        const float* q1 = (const float*)&pb1;
        #pragma unroll
        for (int u = 0; u < 4; u++) {
            float h0 = tf32_rna(q0[u]);
            Bh[bkk * 136 + bn4 + u] = h0;
            Bl[bkk * 136 + bn4 + u] = tf32_rna(q0[u] - h0);
            float h1 = tf32_rna(q1[u]);
            Bh[(bkk + 8) * 136 + bn4 + u] = h1;
            Bl[(bkk + 8) * 136 + bn4 + u] = tf32_rna(q1[u] - h1);
        }
    };

    ldTiles(0);
    stTiles(sb);
    __syncthreads();

    int ph = 0;
    for (int k0 = 0; k0 < CC; k0 += 16, ph ^= 1) {
        float* cur = sb + ph * K1_BUF;
        float* nxt = sb + (ph ^ 1) * K1_BUF;
        const bool more = (k0 + 16 < CC);
        if (more) ldTiles(k0 + 16);

        float* Ah = cur;        float* Al = cur + 2560;
        float* Bh = cur + 5120; float* Bl = cur + 7296;
        #pragma unroll
        for (int s = 0; s < 2; s++) {
            float ah[4][4], al[4][4], bh[4][2], bl[4][2];
            #pragma unroll
            for (int i = 0; i < 4; i++) {
                int r0 = (m0w + 16 * i + lrow) * 20, c0 = 8 * s + lcol;
                ah[i][0] = Ah[r0 + c0];       ah[i][1] = Ah[r0 + 160 + c0];
                ah[i][2] = Ah[r0 + c0 + 4];   ah[i][3] = Ah[r0 + 160 + c0 + 4];
                al[i][0] = Al[r0 + c0];       al[i][1] = Al[r0 + 160 + c0];
                al[i][2] = Al[r0 + c0 + 4];   al[i][3] = Al[r0 + 160 + c0 + 4];
            }
            #pragma unroll
            for (int j = 0; j < 4; j++) {
                int cn = n0w + 8 * j + lrow, kr = (8 * s + lcol) * 136;
                bh[j][0] = Bh[kr + cn]; bh[j][1] = Bh[kr + 4 * 136 + cn];
                bl[j][0] = Bl[kr + cn]; bl[j][1] = Bl[kr + 4 * 136 + cn];
            }
            #pragma unroll
            for (int i = 0; i < 4; i++)
                #pragma unroll
                for (int j = 0; j < 4; j++) {
                    mma8(acc[i][j], al[i][0], al[i][1], al[i][2], al[i][3], bh[j][0], bh[j][1]);
                    mma8(acc[i][j], ah[i][0], ah[i][1], ah[i][2], ah[i][3], bl[j][0], bl[j][1]);
                    mma8(acc[i][j], ah[i][0], ah[i][1], ah[i][2], ah[i][3], bh[j][0], bh[j][1]);
                }
        }
        if (more) stTiles(nxt);
        __syncthreads();
    }

    #pragma unroll
    for (int i = 0; i < 4; i++) {
        int m = m0w + 16 * i + lrow;
        const bool isK = (m >= 64);
        int mm = isK ? m - 64 : m;
        float bi0 = isK ? bk[mm] : bq[mm];
        float bi1 = isK ? bk[mm + 8] : bq[mm + 8];
        float* dst = (isK ? g_Kf : g_Qf) + (size_t)b * DD * NN;
        #pragma unroll
        for (int j = 0; j < 4; j++) {
            int n = n0 + n0w + 8 * j + 2 * lcol;
            float2 v0 = { delu_f(acc[i][j][0] + bi0), delu_f(acc[i][j][1] + bi0) };
            *(float2*)(dst + (size_t)mm * NN + n) = v0;
            float2 v1 = { delu_f(acc[i][j][2] + bi1), delu_f(acc[i][j][3] + bi1) };
            *(float2*)(dst + (size_t)(mm + 8) * NN + n) = v1;
        }
    }
}

// ---------------------------------------------------------------------------
// Ksum: g_Ksum[b][m] = sum_n g_Kf[b][m][n].  grid (DD, BB), 256 thr.
// ---------------------------------------------------------------------------
__global__ __launch_bounds__(256) void k_ksum()
{
    const int m = blockIdx.x, b = blockIdx.y;
    const float* src = g_Kf + ((size_t)b * DD + m) * NN;
    float s0 = 0.f, s1 = 0.f;
    for (int i = threadIdx.x; i < NN / 8; i += 256) {
        float4 v = ((const float4*)src)[i];
        float4 w = ((const float4*)src)[i + NN / 8];
        s0 += (v.x + v.y) + (v.z + v.w);
        s1 += (w.x + w.y) + (w.z + w.w);
    }
    __shared__ float red[256];
    red[threadIdx.x] = s0 + s1;
    __syncthreads();
    for (int off = 128; off > 0; off >>= 1) {
        if (threadIdx.x < off) red[threadIdx.x] += red[threadIdx.x + off];
        __syncthreads();
    }
    if (threadIdx.x == 0) g_Ksum[b * DD + m] = red[0];
}

// ---------------------------------------------------------------------------
// K2 (tf32): KXp[s][b][d][e] = sum_{n in split} Kf[d][n]*x[e][n]
// Block 64x128(e), Kchunk=32, K=512/split. grid (4, 8, 8) = 256.
// Ping-pong double-buffered, one sync per iter.
// Buffer: As[64][36] @0 (2304), Bs[128][36] @2304 (4608). Buf=6912 fl; 55,296 B.
// ---------------------------------------------------------------------------
#define K2_BUF 6912
__global__ __launch_bounds__(256) void k2_kx(const float* __restrict__ x)
{
    extern __shared__ float sb[];
    const int e0 = blockIdx.x * 128, b = blockIdx.y, sp = blockIdx.z;
    const int nbase = sp * (NN / KSPLIT);
    const int tid = threadIdx.x, wid = tid >> 5, lane = tid & 31;
    const int lrow = lane >> 2, lcol = lane & 3;
    const int m0w = (wid >> 2) * 32, e0w = (wid & 3) * 32;

    float acc[2][4][4];
    #pragma unroll
    for (int i = 0; i < 2; i++)
        #pragma unroll
        for (int j = 0; j < 4; j++)
            #pragma unroll
            for (int u = 0; u < 4; u++) acc[i][j][u] = 0.f;

    const float* kf = g_Kf + (size_t)b * DD * NN + nbase;
    const float* xb = x + (size_t)b * CC * NN + nbase;
    const int arow = tid >> 3, ac4 = (tid & 7) * 4;

    float4 pa[2], pb[4];
    auto ldTiles = [&](int k0) {
        pa[0] = *(const float4*)(kf + (size_t)arow * NN + k0 + ac4);
        pa[1] = *(const float4*)(kf + (size_t)(arow + 32) * NN + k0 + ac4);
        #pragma unroll
        for (int r = 0; r < 4; r++)
            pb[r] = *(const float4*)(xb + (size_t)(e0 + arow + 32 * r) * NN + k0 + ac4);
    };
    auto stTiles = [&](float* buf) {
        float* As = buf; float* Bs = buf + 2304;
        #pragma unroll
        for (int u = 0; u < 4; u++) {
            As[arow * 36 + ac4 + u]        = tf32_rna(((const float*)&pa[0])[u]);
            As[(arow + 32) * 36 + ac4 + u] = tf32_rna(((const float*)&pa[1])[u]);
        }
        #pragma unroll
        for (int r = 0; r < 4; r++)
            #pragma unroll
            for (int u = 0; u < 4; u++)
                Bs[(arow + 32 * r) * 36 + ac4 + u] = tf32_rna(((const float*)&pb[r])[u]);
    };

    ldTiles(0);
    stTiles(sb);
    __syncthreads();

    int ph = 0;
    for (int k0 = 0; k0 < NN / KSPLIT; k0 += 32, ph ^= 1) {
        float* cur = sb + ph * K2_BUF;
        float* nxt = sb + (ph ^ 1) * K2_BUF;
        const bool more = (k0 + 32 < NN / KSPLIT);
        if (more) ldTiles(k0 + 32);

        float* As = cur; float* Bs = cur + 2304;
        #pragma unroll
        for (int s = 0; s < 4; s++) {
            float a[2][4], bb[4][2];
            #pragma unroll
            for (int i = 0; i < 2; i++) {
                int r0 = (m0w + 16 * i + lrow) * 36, c0 = 8 * s + lcol;
                a[i][0] = As[r0 + c0];      a[i][1] = As[r0 + 8 * 36 + c0];
                a[i][2] = As[r0 + c0 + 4];  a[i][3] = As[r0 + 8 * 36 + c0 + 4];
            }
            #pragma unroll
            for (int j = 0; j < 4; j++) {
                int er = (e0w + 8 * j + lrow) * 36;
                bb[j][0] = Bs[er + 8 * s + lcol]; bb[j][1] = Bs[er + 8 * s + lcol + 4];
            }
            #pragma unroll
            for (int i = 0; i < 2; i++)
                #pragma unroll
                for (int j = 0; j < 4; j++)
                    mma8(acc[i][j], a[i][0], a[i][1], a[i][2], a[i][3], bb[j][0], bb[j][1]);
        }
        if (more) stTiles(nxt);
        __syncthreads();
    }

    float* dst = g_KXp + (size_t)(sp * BB + b) * DD * CC;
    #pragma unroll
    for (int i = 0; i < 2; i++) {
        int d = m0w + 16 * i + lrow;
        #pragma unroll
        for (int j = 0; j < 4; j++) {
            int e = e0 + e0w + 8 * j + 2 * lcol;
            float2 v0 = { acc[i][j][0], acc[i][j][1] };
            *(float2*)(dst + (size_t)d * CC + e) = v0;
            float2 v1 = { acc[i][j][2], acc[i][j][3] };
            *(float2*)(dst + (size_t)(d + 8) * CC + e) = v1;
        }
    }
}

// ---------------------------------------------------------------------------
// sumKX: g_KX = sum over KSPLIT of g_KXp. grid 128, 256 thr, 2 float4/thread.
// ---------------------------------------------------------------------------
__global__ __launch_bounds__(256) void k_sumkx()
{
    const int i = blockIdx.x * 512 + threadIdx.x;
    const int stride = BB * DD * CC / 4;
    const float4* p = (const float4*)g_KXp;
    float4 v0[KSPLIT], v1[KSPLIT];
    #pragma unroll
    for (int sp = 0; sp < KSPLIT; sp++) {
        v0[sp] = p[(size_t)sp * stride + i];
        v1[sp] = p[(size_t)sp * stride + i + 256];
    }
    float4 s0 = v0[0], s1 = v1[0];
    #pragma unroll
    for (int sp = 1; sp < KSPLIT; sp++) {
        s0.x += v0[sp].x; s0.y += v0[sp].y; s0.z += v0[sp].z; s0.w += v0[sp].w;
        s1.x += v1[sp].x; s1.y += v1[sp].y; s1.z += v1[sp].z; s1.w += v1[sp].w;
    }
    ((float4*)g_KX)[i] = s0;
    ((float4*)g_KX)[i + 256] = s1;
}

// ---------------------------------------------------------------------------
// K3 (tf32): KVp[sp][b][d][c] = sum_{e in 128-split} KX[d][e]*wv[c][e]
// Block 64x128(c), K=128 (4 chunks). grid (4, 8, ESPLIT=4) = 128.
// ---------------------------------------------------------------------------
__global__ __launch_bounds__(256) void k3_kv(const float* __restrict__ wv)
{
    const int c0 = blockIdx.x * 128, b = blockIdx.y, sp = blockIdx.z;
    const int ebase = sp * (CC / ESPLIT);
    __shared__ float As[64][36];
    __shared__ float Bs[128][36];
    const int tid = threadIdx.x, wid = tid >> 5, lane = tid & 31;
    const int lrow = lane >> 2, lcol = lane & 3;
    const int m0w = (wid >> 2) * 32, c0w = (wid & 3) * 32;

    float acc[2][4][4];
    #pragma unroll
    for (int i = 0; i < 2; i++)
        #pragma unroll
        for (int j = 0; j < 4; j++)
            #pragma unroll
            for (int u = 0; u < 4; u++) acc[i][j][u] = 0.f;

    const float* kx = g_KX + (size_t)b * DD * CC + ebase;
    const int arow = tid >> 3, ac4 = (tid & 7) * 4;

    for (int k0 = 0; k0 < CC / ESPLIT; k0 += 32) {
        {
            float4 v0 = *(const float4*)(kx + (size_t)arow * CC + k0 + ac4);
            float4 v1 = *(const float4*)(kx + (size_t)(arow + 32) * CC + k0 + ac4);
            #pragma unroll
            for (int u = 0; u < 4; u++) {
                As[arow][ac4 + u]      = tf32_rna(((const float*)&v0)[u]);
                As[arow + 32][ac4 + u] = tf32_rna(((const float*)&v1)[u]);
            }
            #pragma unroll
            for (int r = 0; r < 4; r++) {
                float4 v = *(const float4*)(wv +
                    (size_t)(c0 + arow + 32 * r) * CC + ebase + k0 + ac4);
                #pragma unroll
                for (int u = 0; u < 4; u++)
                    Bs[arow + 32 * r][ac4 + u] = tf32_rna(((const float*)&v)[u]);
            }
        }
        __syncthreads();
        #pragma unroll
        for (int s = 0; s < 4; s++) {
            float a[2][4], bb[4][2];
            #pragma unroll
            for (int i = 0; i < 2; i++) {
                int r0 = m0w + 16 * i + lrow, cc0 = 8 * s + lcol;
                a[i][0] = As[r0][cc0];     a[i][1] = As[r0 + 8][cc0];
                a[i][2] = As[r0][cc0 + 4]; a[i][3] = As[r0 + 8][cc0 + 4];
            }
            #pragma unroll
            for (int j = 0; j < 4; j++) {
                int cr = c0w + 8 * j + lrow;
                bb[j][0] = Bs[cr][8 * s + lcol]; bb[j][1] = Bs[cr][8 * s + lcol + 4];
            }
            #pragma unroll
            for (int i = 0; i < 2; i++)
                #pragma unroll
                for (int j = 0; j < 4; j++)
                    mma8(acc[i][j], a[i][0], a[i][1], a[i][2], a[i][3], bb[j][0], bb[j][1]);
        }
        __syncthreads();
    }

    float* dst = g_KVp + (size_t)(sp * BB + b) * DD * CC;
    #pragma unroll
    for (int i = 0; i < 2; i++) {
        int d = m0w + 16 * i + lrow;
        #pragma unroll
        for (int j = 0; j < 4; j++) {
            int c = c0 + c0w + 8 * j + 2 * lcol;
            float2 v0 = { acc[i][j][0], acc[i][j][1] };
            *(float2*)(dst + (size_t)d * CC + c) = v0;
            float2 v1 = { acc[i][j][2], acc[i][j][3] };
            *(float2*)(dst + (size_t)(d + 8) * CC + c) = v1;
        }
    }
}

// ---------------------------------------------------------------------------
// K4 (tf32): out[c][n] = x[c][n] + gamma*norm[n]*sum_d KV[d][c]*Qf[d][n]
// KV[d][c] = sum_sp KVp[sp][d][c] + bv[c]*Ksum[d] (folded into As build).
// Persistent over c: grid (32, 8); block loads Qf/norm once, loops 4 c-tiles.
// 8 warps: 4Mx2N, warp 32x64. Dynamic smem 70,400 B.
// ---------------------------------------------------------------------------
__global__ __launch_bounds__(256) void k4_out(
    const float* __restrict__ x, const float* __restrict__ bv,
    const float* __restrict__ gamma, float* __restrict__ out)
{
    extern __shared__ float sm[];
    float (*As)[136] = (float(*)[136])sm;                // [64][136]  KV[d][c]
    float (*Bs)[136] = (float(*)[136])(sm + 64 * 136);   // [64][136]  Qf[d][n]
    float* ksumS = sm + 2 * 64 * 136;                     // [64] (+eps)
    float* normS = ksumS + 64;                            // [128]

    const int n0 = blockIdx.x * 128, b = blockIdx.y;
    const int tid = threadIdx.x, wid = tid >> 5, lane = tid & 31;
    const int lrow = lane >> 2, lcol = lane & 3;
    const int m0w = (wid >> 1) * 32, n0w = (wid & 1) * 64;

    // Qf tile -> Bs (once)
    #pragma unroll
    for (int r = 0; r < 8; r++) {
        int idx = tid + r * 256;
        int d = idx >> 5, n4 = (idx & 31) * 4;
        float4 v = *(const float4*)(g_Qf + ((size_t)b * DD + d) * NN + n0 + n4);
        #pragma unroll
        for (int u = 0; u < 4; u++) Bs[d][n4 + u] = tf32_rna(((const float*)&v)[u]);
    }
    if (tid < 64) ksumS[tid] = g_Ksum[b * DD + tid] + 1e-10f;
    __syncthreads();

    if (tid < 128) {
        float s = 0.f;
        #pragma unroll
        for (int d = 0; d < 64; d++) s = fmaf(Bs[d][tid], ksumS[d], s);
        normS[tid] = 1.0f / s;
    }
    const float g = gamma[0];

    for (int ct = 0; ct < CC / 128; ct++) {
        const int c0 = ct * 128;
        __syncthreads();   // prior mma readers of As done (also covers normS 1st iter)
        // KV tile -> As (sum ESPLIT partials + bias term)
        #pragma unroll
        for (int r = 0; r < 8; r++) {
            int idx = tid + r * 256;
            int d = idx >> 5, c4 = (idx & 31) * 4;
            float4 s = *(const float4*)(g_KVp + ((size_t)b * DD + d) * CC + c0 + c4);
            #pragma unroll
            for (int sp = 1; sp < ESPLIT; sp++) {
                float4 v = *(const float4*)(g_KVp +
                    ((size_t)(sp * BB + b) * DD + d) * CC + c0 + c4);
                s.x += v.x; s.y += v.y; s.z += v.z; s.w += v.w;
            }
            float4 bvv = *(const float4*)(bv + c0 + c4);
            float ks = g_Ksum[b * DD + d];
            As[d][c4 + 0] = tf32_rna(s.x + bvv.x * ks);
            As[d][c4 + 1] = tf32_rna(s.y + bvv.y * ks);
            As[d][c4 + 2] = tf32_rna(s.z + bvv.z * ks);
            As[d][c4 + 3] = tf32_rna(s.w + bvv.w * ks);
        }
        __syncthreads();

        float acc[2][8][4];
        #pragma unroll
        for (int i = 0; i < 2; i++)
            #pragma unroll
            for (int j = 0; j < 8; j++)
                #pragma unroll
                for (int u = 0; u < 4; u++) acc[i][j][u] = 0.f;

        #pragma unroll
        for (int s = 0; s < 8; s++) {
            float a[2][4], bb[8][2];
            #pragma unroll
            for (int i = 0; i < 2; i++) {
                int cm = m0w + 16 * i + lrow, kb = 8 * s + lcol;
                a[i][0] = As[kb][cm];     a[i][1] = As[kb][cm + 8];
                a[i][2] = As[kb + 4][cm]; a[i][3] = As[kb + 4][cm + 8];
            }
            #pragma unroll
            for (int j = 0; j < 8; j++) {
                int nc = n0w + 8 * j + lrow;
                bb[j][0] = Bs[8 * s + lcol][nc]; bb[j][1] = Bs[8 * s + lcol + 4][nc];
            }
            #pragma unroll
            for (int i = 0; i < 2; i++)
                #pragma unroll
                for (int j = 0; j < 8; j++)
                    mma8(acc[i][j], a[i][0], a[i][1], a[i][2], a[i][3], bb[j][0], bb[j][1]);
        }

        #pragma unroll
        for (int i = 0; i < 2; i++) {
            int c = c0 + m0w + 16 * i + lrow;
            #pragma unroll
            for (int j = 0; j < 8; j++) {
                int nl = n0w + 8 * j + 2 * lcol;
                int n = n0 + nl;
                float2 nr = *(float2*)&normS[nl];
                const float* xp0 = x + ((size_t)b * CC + c) * NN + n;
                float*       op0 = out + ((size_t)b * CC + c) * NN + n;
                float2 xv0 = *(const float2*)xp0;
                float2 o0 = { xv0.x + g * nr.x * acc[i][j][0],
                              xv0.y + g * nr.y * acc[i][j][1] };
                *(float2*)op0 = o0;
                const float* xp1 = x + ((size_t)b * CC + c + 8) * NN + n;
                float*       op1 = out + ((size_t)b * CC + c + 8) * NN + n;
                float2 xv1 = *(const float2*)xp1;
                float2 o1 = { xv1.x + g * nr.x * acc[i][j][2],
                              xv1.y + g * nr.y * acc[i][j][3] };
                *(float2*)op1 = o1;
            }
        }
    }
}

// ---------------------------------------------------------------------------
extern "C" void kernel_launch(void* const* d_in, const int* in_sizes, int n_in,
                              void* d_out, int out_size)
{
    const float* x     = (const float*)d_in[0];
    const float* wq    = (const float*)d_in[1];
    const float* bq    = (const float*)d_in[2];
    const float* wk    = (const float*)d_in[3];
    const float* bk    = (const float*)d_in[4];
    const float* wv    = (const float*)d_in[5];
    const float* bv    = (const float*)d_in[6];
    const float* gamma = (const float*)d_in[7];
    float* out = (float*)d_out;

    (void)in_sizes; (void)n_in; (void)out_size;

    cudaFuncSetAttribute(k1_qk, cudaFuncAttributeMaxDynamicSharedMemorySize, 75776);
    cudaFuncSetAttribute(k2_kx, cudaFuncAttributeMaxDynamicSharedMemorySize, 55296);
    cudaFuncSetAttribute(k4_out, cudaFuncAttributeMaxDynamicSharedMemorySize, 70400);

    k1_qk  <<<dim3(NN / 128, BB),          256, 75776>>>(x, wq, bq, wk, bk);
    k_ksum <<<dim3(DD, BB),                256>>>();
    k2_kx  <<<dim3(CC / 128, BB, KSPLIT),  256, 55296>>>(x);
    k_sumkx<<<dim3(128),                   256>>>();
    k3_kv  <<<dim3(CC / 128, BB, ESPLIT),  256>>>(wv);
    k4_out <<<dim3(NN / 128, BB),          256, 70400>>>(x, bv, gamma, out);
}

// round 5
// speedup vs baseline: 2.6707x; 1.2056x over previous
#include <cuda_runtime.h>

#define BB 8
#define CC 512
#define DD 64
#define NN 4096
#define KSPLIT 8      // k2 split-K over n

// Scratch (device globals). ~26 MB.
__device__ float g_Qf[BB * DD * NN];             // delu(Q)  8 MB
__device__ float g_Kf[BB * DD * NN];             // delu(K)  8 MB
__device__ float g_Ksum[BB * DD];
__device__ float g_KXp[KSPLIT * BB * DD * CC];   // split-K partials of Kf@X^T
__device__ float g_KX[BB * DD * CC];             // summed
__device__ float g_KV[BB * DD * CC];             // final KV (incl. bv*Ksum)

__device__ __forceinline__ float delu_f(float v) {
    return v > 0.f ? fmaf(10.f, v, 1.f) : __expf(10.f * v);
}
__device__ __forceinline__ float tf32_rna(float f) {
    unsigned u;
    asm("cvt.rna.tf32.f32 %0, %1;" : "=r"(u) : "f"(f));
    return __uint_as_float(u);
}
__device__ __forceinline__ void mma8(float c[4], float a0, float a1, float a2, float a3,
                                     float b0, float b1) {
    unsigned A0 = __float_as_uint(a0), A1 = __float_as_uint(a1);
    unsigned A2 = __float_as_uint(a2), A3 = __float_as_uint(a3);
    unsigned B0 = __float_as_uint(b0), B1 = __float_as_uint(b1);
    asm volatile(
        "mma.sync.aligned.m16n8k8.row.col.f32.tf32.tf32.f32 "
        "{%0,%1,%2,%3}, {%4,%5,%6,%7}, {%8,%9}, {%0,%1,%2,%3};"
        : "+f"(c[0]), "+f"(c[1]), "+f"(c[2]), "+f"(c[3])
        : "r"(A0), "r"(A1), "r"(A2), "r"(A3), "r"(B0), "r"(B1));
}

// ---------------------------------------------------------------------------
// K1 (single-pass tf32, fused Q+K): [wq;wk](128x512) @ X(512x4096) + bias -> delu
// Block 128x128, Kchunk=16, 8 warps (2Mx4N), warp 64x32. grid (32, 8).
// Ping-pong double buffered, one sync per iter.
// Buffer: A[128][20] @0 (2560), B[16][136] @2560 (2176). Buf=4736 fl; 37,888 B.
// ---------------------------------------------------------------------------
#define K1_BUF 4736
__global__ __launch_bounds__(256) void k1_qk(
    const float* __restrict__ x,  const float* __restrict__ wq,
    const float* __restrict__ bq, const float* __restrict__ wk,
    const float* __restrict__ bk)
{
    extern __shared__ float sb[];
    const int b = blockIdx.y;
    const int n0 = blockIdx.x * 128;
    const int tid = threadIdx.x, wid = tid >> 5, lane = tid & 31;
    const int lrow = lane >> 2, lcol = lane & 3;
    const int m0w = (wid >> 2) * 64, n0w = (wid & 3) * 32;

    float acc[4][4][4];
    #pragma unroll
    for (int i = 0; i < 4; i++)
        #pragma unroll
        for (int j = 0; j < 4; j++)
            #pragma unroll
            for (int u = 0; u < 4; u++) acc[i][j][u] = 0.f;

    const float* xb = x + (size_t)b * CC * NN;
    const int arow = tid >> 2, ac4 = (tid & 3) * 4;     // A rows arow (wq) / arow+64 (wk)
    const int bkk = tid >> 5, bn4 = (tid & 31) * 4;     // B rows bkk / bkk+8

    float4 pa0, pa1, pb0, pb1;
    auto ldTiles = [&](int k0) {
        pa0 = *(const float4*)(wq + (size_t)arow * CC + k0 + ac4);
        pa1 = *(const float4*)(wk + (size_t)arow * CC + k0 + ac4);
        pb0 = *(const float4*)(xb + (size_t)(k0 + bkk) * NN + n0 + bn4);
        pb1 = *(const float4*)(xb + (size_t)(k0 + 8 + bkk) * NN + n0 + bn4);
    };
    auto stTiles = [&](float* buf) {
        float* A = buf; float* B = buf + 2560;
        #pragma unroll
        for (int u = 0; u < 4; u++) {
            A[arow * 20 + ac4 + u]        = tf32_rna(((const float*)&pa0)[u]);
            A[(arow + 64) * 20 + ac4 + u] = tf32_rna(((const float*)&pa1)[u]);
            B[bkk * 136 + bn4 + u]        = tf32_rna(((const float*)&pb0)[u]);
            B[(bkk + 8) * 136 + bn4 + u]  = tf32_rna(((const float*)&pb1)[u]);
        }
    };

    ldTiles(0);
    stTiles(sb);
    __syncthreads();

    int ph = 0;
    for (int k0 = 0; k0 < CC; k0 += 16, ph ^= 1) {
        float* cur = sb + ph * K1_BUF;
        float* nxt = sb + (ph ^ 1) * K1_BUF;
        const bool more = (k0 + 16 < CC);
        if (more) ldTiles(k0 + 16);

        float* A = cur; float* B = cur + 2560;
        #pragma unroll
        for (int s = 0; s < 2; s++) {
            float a[4][4], bb[4][2];
            #pragma unroll
            for (int i = 0; i < 4; i++) {
                int r0 = (m0w + 16 * i + lrow) * 20, c0 = 8 * s + lcol;
                a[i][0] = A[r0 + c0];       a[i][1] = A[r0 + 160 + c0];
                a[i][2] = A[r0 + c0 + 4];   a[i][3] = A[r0 + 160 + c0 + 4];
            }
            #pragma unroll
            for (int j = 0; j < 4; j++) {
                int cn = n0w + 8 * j + lrow, kr = (8 * s + lcol) * 136;
                bb[j][0] = B[kr + cn]; bb[j][1] = B[kr + 4 * 136 + cn];
            }
            #pragma unroll
            for (int i = 0; i < 4; i++)
                #pragma unroll
                for (int j = 0; j < 4; j++)
                    mma8(acc[i][j], a[i][0], a[i][1], a[i][2], a[i][3], bb[j][0], bb[j][1]);
        }
        if (more) stTiles(nxt);
        __syncthreads();
    }

    #pragma unroll
    for (int i = 0; i < 4; i++) {
        int m = m0w + 16 * i + lrow;
        const bool isK = (m >= 64);
        int mm = isK ? m - 64 : m;
        float bi0 = isK ? bk[mm] : bq[mm];
        float bi1 = isK ? bk[mm + 8] : bq[mm + 8];
        float* dst = (isK ? g_Kf : g_Qf) + (size_t)b * DD * NN;
        #pragma unroll
        for (int j = 0; j < 4; j++) {
            int n = n0 + n0w + 8 * j + 2 * lcol;
            float2 v0 = { delu_f(acc[i][j][0] + bi0), delu_f(acc[i][j][1] + bi0) };
            *(float2*)(dst + (size_t)mm * NN + n) = v0;
            float2 v1 = { delu_f(acc[i][j][2] + bi1), delu_f(acc[i][j][3] + bi1) };
            *(float2*)(dst + (size_t)(mm + 8) * NN + n) = v1;
        }
    }
}

// ---------------------------------------------------------------------------
// Ksum: g_Ksum[b][m] = sum_n g_Kf[b][m][n].  grid (DD, BB), 256 thr.
// ---------------------------------------------------------------------------
__global__ __launch_bounds__(256) void k_ksum()
{
    const int m = blockIdx.x, b = blockIdx.y;
    const float* src = g_Kf + ((size_t)b * DD + m) * NN;
    float s0 = 0.f, s1 = 0.f;
    for (int i = threadIdx.x; i < NN / 8; i += 256) {
        float4 v = ((const float4*)src)[i];
        float4 w = ((const float4*)src)[i + NN / 8];
        s0 += (v.x + v.y) + (v.z + v.w);
        s1 += (w.x + w.y) + (w.z + w.w);
    }
    __shared__ float red[256];
    red[threadIdx.x] = s0 + s1;
    __syncthreads();
    for (int off = 128; off > 0; off >>= 1) {
        if (threadIdx.x < off) red[threadIdx.x] += red[threadIdx.x + off];
        __syncthreads();
    }
    if (threadIdx.x == 0) g_Ksum[b * DD + m] = red[0];
}

// ---------------------------------------------------------------------------
// K2 (tf32): KXp[s][b][d][e] = sum_{n in split} Kf[d][n]*x[e][n]
// Block 64x128(e), Kchunk=32, K=512/split. grid (4, 8, 8) = 256.
// Ping-pong double-buffered, one sync per iter.
// Buffer: As[64][36] @0 (2304), Bs[128][36] @2304 (4608). Buf=6912 fl; 55,296 B.
// ---------------------------------------------------------------------------
#define K2_BUF 6912
__global__ __launch_bounds__(256) void k2_kx(const float* __restrict__ x)
{
    extern __shared__ float sb[];
    const int e0 = blockIdx.x * 128, b = blockIdx.y, sp = blockIdx.z;
    const int nbase = sp * (NN / KSPLIT);
    const int tid = threadIdx.x, wid = tid >> 5, lane = tid & 31;
    const int lrow = lane >> 2, lcol = lane & 3;
    const int m0w = (wid >> 2) * 32, e0w = (wid & 3) * 32;

    float acc[2][4][4];
    #pragma unroll
    for (int i = 0; i < 2; i++)
        #pragma unroll
        for (int j = 0; j < 4; j++)
            #pragma unroll
            for (int u = 0; u < 4; u++) acc[i][j][u] = 0.f;

    const float* kf = g_Kf + (size_t)b * DD * NN + nbase;
    const float* xb = x + (size_t)b * CC * NN + nbase;
    const int arow = tid >> 3, ac4 = (tid & 7) * 4;

    float4 pa[2], pb[4];
    auto ldTiles = [&](int k0) {
        pa[0] = *(const float4*)(kf + (size_t)arow * NN + k0 + ac4);
        pa[1] = *(const float4*)(kf + (size_t)(arow + 32) * NN + k0 + ac4);
        #pragma unroll
        for (int r = 0; r < 4; r++)
            pb[r] = *(const float4*)(xb + (size_t)(e0 + arow + 32 * r) * NN + k0 + ac4);
    };
    auto stTiles = [&](float* buf) {
        float* As = buf; float* Bs = buf + 2304;
        #pragma unroll
        for (int u = 0; u < 4; u++) {
            As[arow * 36 + ac4 + u]        = tf32_rna(((const float*)&pa[0])[u]);
            As[(arow + 32) * 36 + ac4 + u] = tf32_rna(((const float*)&pa[1])[u]);
        }
        #pragma unroll
        for (int r = 0; r < 4; r++)
            #pragma unroll
            for (int u = 0; u < 4; u++)
                Bs[(arow + 32 * r) * 36 + ac4 + u] = tf32_rna(((const float*)&pb[r])[u]);
    };

    ldTiles(0);
    stTiles(sb);
    __syncthreads();

    int ph = 0;
    for (int k0 = 0; k0 < NN / KSPLIT; k0 += 32, ph ^= 1) {
        float* cur = sb + ph * K2_BUF;
        float* nxt = sb + (ph ^ 1) * K2_BUF;
        const bool more = (k0 + 32 < NN / KSPLIT);
        if (more) ldTiles(k0 + 32);

        float* As = cur; float* Bs = cur + 2304;
        #pragma unroll
        for (int s = 0; s < 4; s++) {
            float a[2][4], bb[4][2];
            #pragma unroll
            for (int i = 0; i < 2; i++) {
                int r0 = (m0w + 16 * i + lrow) * 36, c0 = 8 * s + lcol;
                a[i][0] = As[r0 + c0];      a[i][1] = As[r0 + 8 * 36 + c0];
                a[i][2] = As[r0 + c0 + 4];  a[i][3] = As[r0 + 8 * 36 + c0 + 4];
            }
            #pragma unroll
            for (int j = 0; j < 4; j++) {
                int er = (e0w + 8 * j + lrow) * 36;
                bb[j][0] = Bs[er + 8 * s + lcol]; bb[j][1] = Bs[er + 8 * s + lcol + 4];
            }
            #pragma unroll
            for (int i = 0; i < 2; i++)
                #pragma unroll
                for (int j = 0; j < 4; j++)
                    mma8(acc[i][j], a[i][0], a[i][1], a[i][2], a[i][3], bb[j][0], bb[j][1]);
        }
        if (more) stTiles(nxt);
        __syncthreads();
    }

    float* dst = g_KXp + (size_t)(sp * BB + b) * DD * CC;
    #pragma unroll
    for (int i = 0; i < 2; i++) {
        int d = m0w + 16 * i + lrow;
        #pragma unroll
        for (int j = 0; j < 4; j++) {
            int e = e0 + e0w + 8 * j + 2 * lcol;
            float2 v0 = { acc[i][j][0], acc[i][j][1] };
            *(float2*)(dst + (size_t)d * CC + e) = v0;
            float2 v1 = { acc[i][j][2], acc[i][j][3] };
            *(float2*)(dst + (size_t)(d + 8) * CC + e) = v1;
        }
    }
}

// ---------------------------------------------------------------------------
// sumKX: g_KX = sum over KSPLIT of g_KXp. grid 128, 256 thr, 2 float4/thread.
// ---------------------------------------------------------------------------
__global__ __launch_bounds__(256) void k_sumkx()
{
    const int i = blockIdx.x * 512 + threadIdx.x;
    const int stride = BB * DD * CC / 4;
    const float4* p = (const float4*)g_KXp;
    float4 v0[KSPLIT], v1[KSPLIT];
    #pragma unroll
    for (int sp = 0; sp < KSPLIT; sp++) {
        v0[sp] = p[(size_t)sp * stride + i];
        v1[sp] = p[(size_t)sp * stride + i + 256];
    }
    float4 s0 = v0[0], s1 = v1[0];
    #pragma unroll
    for (int sp = 1; sp < KSPLIT; sp++) {
        s0.x += v0[sp].x; s0.y += v0[sp].y; s0.z += v0[sp].z; s0.w += v0[sp].w;
        s1.x += v1[sp].x; s1.y += v1[sp].y; s1.z += v1[sp].z; s1.w += v1[sp].w;
    }
    ((float4*)g_KX)[i] = s0;
    ((float4*)g_KX)[i + 256] = s1;
}

// ---------------------------------------------------------------------------
// K3 (tf32): KV[b][d][c] = sum_e KX[d][e]*wv[c][e] + bv[c]*Ksum[d]  (FINAL)
// Block 64x128(c), K=512 (16 chunks). grid (4, 8) = 32.
// ---------------------------------------------------------------------------
__global__ __launch_bounds__(256) void k3_kv(
    const float* __restrict__ wv, const float* __restrict__ bv)
{
    const int c0 = blockIdx.x * 128, b = blockIdx.y;
    __shared__ float As[64][36];
    __shared__ float Bs[128][36];
    const int tid = threadIdx.x, wid = tid >> 5, lane = tid & 31;
    const int lrow = lane >> 2, lcol = lane & 3;
    const int m0w = (wid >> 2) * 32, c0w = (wid & 3) * 32;

    float acc[2][4][4];
    #pragma unroll
    for (int i = 0; i < 2; i++)
        #pragma unroll
        for (int j = 0; j < 4; j++)
            #pragma unroll
            for (int u = 0; u < 4; u++) acc[i][j][u] = 0.f;

    const float* kx = g_KX + (size_t)b * DD * CC;
    const int arow = tid >> 3, ac4 = (tid & 7) * 4;

    for (int k0 = 0; k0 < CC; k0 += 32) {
        {
            float4 v0 = *(const float4*)(kx + (size_t)arow * CC + k0 + ac4);
            float4 v1 = *(const float4*)(kx + (size_t)(arow + 32) * CC + k0 + ac4);
            #pragma unroll
            for (int u = 0; u < 4; u++) {
                As[arow][ac4 + u]      = tf32_rna(((const float*)&v0)[u]);
                As[arow + 32][ac4 + u] = tf32_rna(((const float*)&v1)[u]);
            }
            #pragma unroll
            for (int r = 0; r < 4; r++) {
                float4 v = *(const float4*)(wv +
                    (size_t)(c0 + arow + 32 * r) * CC + k0 + ac4);
                #pragma unroll
                for (int u = 0; u < 4; u++)
                    Bs[arow + 32 * r][ac4 + u] = tf32_rna(((const float*)&v)[u]);
            }
        }
        __syncthreads();
        #pragma unroll
        for (int s = 0; s < 4; s++) {
            float a[2][4], bb[4][2];
            #pragma unroll
            for (int i = 0; i < 2; i++) {
                int r0 = m0w + 16 * i + lrow, cc0 = 8 * s + lcol;
                a[i][0] = As[r0][cc0];     a[i][1] = As[r0 + 8][cc0];
                a[i][2] = As[r0][cc0 + 4]; a[i][3] = As[r0 + 8][cc0 + 4];
            }
            #pragma unroll
            for (int j = 0; j < 4; j++) {
                int cr = c0w + 8 * j + lrow;
                bb[j][0] = Bs[cr][8 * s + lcol]; bb[j][1] = Bs[cr][8 * s + lcol + 4];
            }
            #pragma unroll
            for (int i = 0; i < 2; i++)
                #pragma unroll
                for (int j = 0; j < 4; j++)
                    mma8(acc[i][j], a[i][0], a[i][1], a[i][2], a[i][3], bb[j][0], bb[j][1]);
        }
        __syncthreads();
    }

    #pragma unroll
    for (int i = 0; i < 2; i++) {
        int d = m0w + 16 * i + lrow;
        float ks0 = g_Ksum[b * DD + d], ks1 = g_Ksum[b * DD + d + 8];
        #pragma unroll
        for (int j = 0; j < 4; j++) {
            int c = c0 + c0w + 8 * j + 2 * lcol;
            float bv0 = bv[c], bv1 = bv[c + 1];
            float2 v0 = { acc[i][j][0] + bv0 * ks0, acc[i][j][1] + bv1 * ks0 };
            *(float2*)(g_KV + ((size_t)b * DD + d) * CC + c) = v0;
            float2 v1 = { acc[i][j][2] + bv0 * ks1, acc[i][j][3] + bv1 * ks1 };
            *(float2*)(g_KV + ((size_t)b * DD + d + 8) * CC + c) = v1;
        }
    }
}

// ---------------------------------------------------------------------------
// K4 (tf32): out[c][n] = x[c][n] + gamma*norm[n]*sum_d KV[d][c]*Qf[d][n]
// Persistent over c: grid (32, 8); loads Qf/norm once, loops 4 c-tiles,
// register-prefetching the next c-tile's KV during the mma phase.
// 8 warps: 4Mx2N, warp 32x64. Dynamic smem 70,400 B.
// ---------------------------------------------------------------------------
__global__ __launch_bounds__(256) void k4_out(
    const float* __restrict__ x, const float* __restrict__ gamma,
    float* __restrict__ out)
{
    extern __shared__ float sm[];
    float (*As)[136] = (float(*)[136])sm;                // [64][136]  KV[d][c]
    float (*Bs)[136] = (float(*)[136])(sm + 64 * 136);   // [64][136]  Qf[d][n]
    float* ksumS = sm + 2 * 64 * 136;                     // [64] (+eps)
    float* normS = ksumS + 64;                            // [128]

    const int n0 = blockIdx.x * 128, b = blockIdx.y;
    const int tid = threadIdx.x, wid = tid >> 5, lane = tid & 31;
    const int lrow = lane >> 2, lcol = lane & 3;
    const int m0w = (wid >> 1) * 32, n0w = (wid & 1) * 64;

    const int kvd = tid >> 5, kvc4 = (tid & 31) * 4;     // As-build coords

    // Qf tile -> Bs (once)
    #pragma unroll
    for (int r = 0; r < 8; r++) {
        int idx = tid + r * 256;
        int d = idx >> 5, n4 = (idx & 31) * 4;
        float4 v = *(const float4*)(g_Qf + ((size_t)b * DD + d) * NN + n0 + n4);
        #pragma unroll
        for (int u = 0; u < 4; u++) Bs[d][n4 + u] = tf32_rna(((const float*)&v)[u]);
    }
    if (tid < 64) ksumS[tid] = g_Ksum[b * DD + tid] + 1e-10f;

    float4 kvreg[8];
    auto ldKV = [&](int c0) {
        #pragma unroll
        for (int r = 0; r < 8; r++)
            kvreg[r] = *(const float4*)(g_KV +
                ((size_t)b * DD + (kvd + 8 * r)) * CC + c0 + kvc4);
    };
    auto stAs = [&]() {
        #pragma unroll
        for (int r = 0; r < 8; r++) {
            int d = kvd + 8 * r;
            As[d][kvc4 + 0] = tf32_rna(kvreg[r].x);
            As[d][kvc4 + 1] = tf32_rna(kvreg[r].y);
            As[d][kvc4 + 2] = tf32_rna(kvreg[r].z);
            As[d][kvc4 + 3] = tf32_rna(kvreg[r].w);
        }
    };

    ldKV(0);
    __syncthreads();

    if (tid < 128) {
        float s = 0.f;
        #pragma unroll
        for (int d = 0; d < 64; d++) s = fmaf(Bs[d][tid], ksumS[d], s);
        normS[tid] = 1.0f / s;
    }
    const float g = gamma[0];

    for (int ct = 0; ct < CC / 128; ct++) {
        const int c0 = ct * 128;
        __syncthreads();   // prior mma readers of As done (1st iter: normS ready)
        stAs();
        __syncthreads();
        if (ct + 1 < CC / 128) ldKV(c0 + 128);   // overlap with mma below

        float acc[2][8][4];
        #pragma unroll
        for (int i = 0; i < 2; i++)
            #pragma unroll
            for (int j = 0; j < 8; j++)
                #pragma unroll
                for (int u = 0; u < 4; u++) acc[i][j][u] = 0.f;

        #pragma unroll
        for (int s = 0; s < 8; s++) {
            float a[2][4], bb[8][2];
            #pragma unroll
            for (int i = 0; i < 2; i++) {
                int cm = m0w + 16 * i + lrow, kb = 8 * s + lcol;
                a[i][0] = As[kb][cm];     a[i][1] = As[kb][cm + 8];
                a[i][2] = As[kb + 4][cm]; a[i][3] = As[kb + 4][cm + 8];
            }
            #pragma unroll
            for (int j = 0; j < 8; j++) {
                int nc = n0w + 8 * j + lrow;
                bb[j][0] = Bs[8 * s + lcol][nc]; bb[j][1] = Bs[8 * s + lcol + 4][nc];
            }
            #pragma unroll
            for (int i = 0; i < 2; i++)
                #pragma unroll
                for (int j = 0; j < 8; j++)
                    mma8(acc[i][j], a[i][0], a[i][1], a[i][2], a[i][3], bb[j][0], bb[j][1]);
        }

        #pragma unroll
        for (int i = 0; i < 2; i++) {
            int c = c0 + m0w + 16 * i + lrow;
            #pragma unroll
            for (int j = 0; j < 8; j++) {
                int nl = n0w + 8 * j + 2 * lcol;
                int n = n0 + nl;
                float2 nr = *(float2*)&normS[nl];
                const float* xp0 = x + ((size_t)b * CC + c) * NN + n;
                float*       op0 = out + ((size_t)b * CC + c) * NN + n;
                float2 xv0 = *(const float2*)xp0;
                float2 o0 = { xv0.x + g * nr.x * acc[i][j][0],
                              xv0.y + g * nr.y * acc[i][j][1] };
                *(float2*)op0 = o0;
                const float* xp1 = x + ((size_t)b * CC + c + 8) * NN + n;
                float*       op1 = out + ((size_t)b * CC + c + 8) * NN + n;
                float2 xv1 = *(const float2*)xp1;
                float2 o1 = { xv1.x + g * nr.x * acc[i][j][2],
                              xv1.y + g * nr.y * acc[i][j][3] };
                *(float2*)op1 = o1;
            }
        }
    }
}

// ---------------------------------------------------------------------------
extern "C" void kernel_launch(void* const* d_in, const int* in_sizes, int n_in,
                              void* d_out, int out_size)
{
    const float* x     = (const float*)d_in[0];
    const float* wq    = (const float*)d_in[1];
    const float* bq    = (const float*)d_in[2];
    const float* wk    = (const float*)d_in[3];
    const float* bk    = (const float*)d_in[4];
    const float* wv    = (const float*)d_in[5];
    const float* bv    = (const float*)d_in[6];
    const float* gamma = (const float*)d_in[7];
    float* out = (float*)d_out;

    (void)in_sizes; (void)n_in; (void)out_size;

    cudaFuncSetAttribute(k2_kx, cudaFuncAttributeMaxDynamicSharedMemorySize, 55296);
    cudaFuncSetAttribute(k4_out, cudaFuncAttributeMaxDynamicSharedMemorySize, 70400);

    k1_qk  <<<dim3(NN / 128, BB),          256, 37888>>>(x, wq, bq, wk, bk);
    k_ksum <<<dim3(DD, BB),                256>>>();
    k2_kx  <<<dim3(CC / 128, BB, KSPLIT),  256, 55296>>>(x);
    k_sumkx<<<dim3(128),                   256>>>();
    k3_kv  <<<dim3(CC / 128, BB),          256>>>(wv, bv);
    k4_out <<<dim3(NN / 128, BB),          256, 70400>>>(x, gamma, out);
}

// round 6
// speedup vs baseline: 3.0439x; 1.1398x over previous
#include <cuda_runtime.h>
#include <cuda_bf16.h>

#define BB 8
#define CC 512
#define DD 64
#define NN 4096
#define KSPLIT 8      // k2 split-K over n
#define ESPLIT 4      // k3 split over e

// Scratch (device globals). ~21 MB.
__device__ __nv_bfloat16 g_Qf[BB * DD * NN];     // delu(Q)  4 MB  [b][d][n]
__device__ __nv_bfloat16 g_Kf[BB * DD * NN];     // delu(K)  4 MB  [b][d][n]
__device__ float g_Ksum[BB * DD];
__device__ float g_KXp[KSPLIT * BB * DD * CC];   // split-K partials of Kf@X^T
__device__ float g_KX[BB * DD * CC];             // summed
__device__ float g_KVp[ESPLIT * BB * DD * CC];   // partials of KX@wv^T
__device__ __nv_bfloat16 g_KVT[BB * CC * DD];    // final KV, transposed [b][c][d]

__device__ __forceinline__ float delu_f(float v) {
    return v > 0.f ? fmaf(10.f, v, 1.f) : __expf(10.f * v);
}
__device__ __forceinline__ float tf32_rna(float f) {
    unsigned u;
    asm("cvt.rna.tf32.f32 %0, %1;" : "=r"(u) : "f"(f));
    return __uint_as_float(u);
}
__device__ __forceinline__ unsigned packbf(float lo, float hi) {
    __nv_bfloat162 h = __floats2bfloat162_rn(lo, hi);   // .x = lo = low half
    return *(unsigned*)&h;
}
// tf32 m16n8k8
__device__ __forceinline__ void mma8(float c[4], float a0, float a1, float a2, float a3,
                                     float b0, float b1) {
    unsigned A0 = __float_as_uint(a0), A1 = __float_as_uint(a1);
    unsigned A2 = __float_as_uint(a2), A3 = __float_as_uint(a3);
    unsigned B0 = __float_as_uint(b0), B1 = __float_as_uint(b1);
    asm volatile(
        "mma.sync.aligned.m16n8k8.row.col.f32.tf32.tf32.f32 "
        "{%0,%1,%2,%3}, {%4,%5,%6,%7}, {%8,%9}, {%0,%1,%2,%3};"
        : "+f"(c[0]), "+f"(c[1]), "+f"(c[2]), "+f"(c[3])
        : "r"(A0), "r"(A1), "r"(A2), "r"(A3), "r"(B0), "r"(B1));
}
// bf16 m16n8k16
__device__ __forceinline__ void mma16(float c[4], unsigned a0, unsigned a1,
                                      unsigned a2, unsigned a3,
                                      unsigned b0, unsigned b1) {
    asm volatile(
        "mma.sync.aligned.m16n8k16.row.col.f32.bf16.bf16.f32 "
        "{%0,%1,%2,%3}, {%4,%5,%6,%7}, {%8,%9}, {%0,%1,%2,%3};"
        : "+f"(c[0]), "+f"(c[1]), "+f"(c[2]), "+f"(c[3])
        : "r"(a0), "r"(a1), "r"(a2), "r"(a3), "r"(b0), "r"(b1));
}

// ---------------------------------------------------------------------------
// K1 (tf32, fused Q+K): [wq;wk](128x512) @ X(512x4096) + bias -> delu -> bf16
// Block 128x128, Kchunk=16, 8 warps (2Mx4N), warp 64x32. grid (32, 8).
// Ping-pong double buffered. Buf = 4736 floats; 37,888 B dynamic smem.
// ---------------------------------------------------------------------------
#define K1_BUF 4736
__global__ __launch_bounds__(256) void k1_qk(
    const float* __restrict__ x,  const float* __restrict__ wq,
    const float* __restrict__ bq, const float* __restrict__ wk,
    const float* __restrict__ bk)
{
    extern __shared__ float sb[];
    const int b = blockIdx.y;
    const int n0 = blockIdx.x * 128;
    const int tid = threadIdx.x, wid = tid >> 5, lane = tid & 31;
    const int lrow = lane >> 2, lcol = lane & 3;
    const int m0w = (wid >> 2) * 64, n0w = (wid & 3) * 32;

    float acc[4][4][4];
    #pragma unroll
    for (int i = 0; i < 4; i++)
        #pragma unroll
        for (int j = 0; j < 4; j++)
            #pragma unroll
            for (int u = 0; u < 4; u++) acc[i][j][u] = 0.f;

    const float* xb = x + (size_t)b * CC * NN;
    const int arow = tid >> 2, ac4 = (tid & 3) * 4;
    const int bkk = tid >> 5, bn4 = (tid & 31) * 4;

    float4 pa0, pa1, pb0, pb1;
    auto ldTiles = [&](int k0) {
        pa0 = *(const float4*)(wq + (size_t)arow * CC + k0 + ac4);
        pa1 = *(const float4*)(wk + (size_t)arow * CC + k0 + ac4);
        pb0 = *(const float4*)(xb + (size_t)(k0 + bkk) * NN + n0 + bn4);
        pb1 = *(const float4*)(xb + (size_t)(k0 + 8 + bkk) * NN + n0 + bn4);
    };
    auto stTiles = [&](float* buf) {
        float* A = buf; float* B = buf + 2560;
        #pragma unroll
        for (int u = 0; u < 4; u++) {
            A[arow * 20 + ac4 + u]        = tf32_rna(((const float*)&pa0)[u]);
            A[(arow + 64) * 20 + ac4 + u] = tf32_rna(((const float*)&pa1)[u]);
            B[bkk * 136 + bn4 + u]        = tf32_rna(((const float*)&pb0)[u]);
            B[(bkk + 8) * 136 + bn4 + u]  = tf32_rna(((const float*)&pb1)[u]);
        }
    };

    ldTiles(0);
    stTiles(sb);
    __syncthreads();

    int ph = 0;
    for (int k0 = 0; k0 < CC; k0 += 16, ph ^= 1) {
        float* cur = sb + ph * K1_BUF;
        float* nxt = sb + (ph ^ 1) * K1_BUF;
        const bool more = (k0 + 16 < CC);
        if (more) ldTiles(k0 + 16);

        float* A = cur; float* B = cur + 2560;
        #pragma unroll
        for (int s = 0; s < 2; s++) {
            float a[4][4], bb[4][2];
            #pragma unroll
            for (int i = 0; i < 4; i++) {
                int r0 = (m0w + 16 * i + lrow) * 20, c0 = 8 * s + lcol;
                a[i][0] = A[r0 + c0];       a[i][1] = A[r0 + 160 + c0];
                a[i][2] = A[r0 + c0 + 4];   a[i][3] = A[r0 + 160 + c0 + 4];
            }
            #pragma unroll
            for (int j = 0; j < 4; j++) {
                int cn = n0w + 8 * j + lrow, kr = (8 * s + lcol) * 136;
                bb[j][0] = B[kr + cn]; bb[j][1] = B[kr + 4 * 136 + cn];
            }
            #pragma unroll
            for (int i = 0; i < 4; i++)
                #pragma unroll
                for (int j = 0; j < 4; j++)
                    mma8(acc[i][j], a[i][0], a[i][1], a[i][2], a[i][3], bb[j][0], bb[j][1]);
        }
        if (more) stTiles(nxt);
        __syncthreads();
    }

    #pragma unroll
    for (int i = 0; i < 4; i++) {
        int m = m0w + 16 * i + lrow;
        const bool isK = (m >= 64);
        int mm = isK ? m - 64 : m;
        float bi0 = isK ? bk[mm] : bq[mm];
        float bi1 = isK ? bk[mm + 8] : bq[mm + 8];
        __nv_bfloat16* dst = (isK ? g_Kf : g_Qf) + (size_t)b * DD * NN;
        #pragma unroll
        for (int j = 0; j < 4; j++) {
            int n = n0 + n0w + 8 * j + 2 * lcol;
            *(__nv_bfloat162*)(dst + (size_t)mm * NN + n) =
                __floats2bfloat162_rn(delu_f(acc[i][j][0] + bi0), delu_f(acc[i][j][1] + bi0));
            *(__nv_bfloat162*)(dst + (size_t)(mm + 8) * NN + n) =
                __floats2bfloat162_rn(delu_f(acc[i][j][2] + bi1), delu_f(acc[i][j][3] + bi1));
        }
    }
}

// ---------------------------------------------------------------------------
// Ksum: g_Ksum[b][m] = sum_n bf16 g_Kf[b][m][n] (fp32 accum). grid (DD, BB).
// ---------------------------------------------------------------------------
__global__ __launch_bounds__(256) void k_ksum()
{
    const int m = blockIdx.x, b = blockIdx.y;
    const __nv_bfloat162* src =
        (const __nv_bfloat162*)(g_Kf + ((size_t)b * DD + m) * NN);
    float s = 0.f;
    for (int i = threadIdx.x; i < NN / 2; i += 256) {
        float2 f = __bfloat1622float2(src[i]);
        s += f.x + f.y;
    }
    __shared__ float red[256];
    red[threadIdx.x] = s;
    __syncthreads();
    for (int off = 128; off > 0; off >>= 1) {
        if (threadIdx.x < off) red[threadIdx.x] += red[threadIdx.x + off];
        __syncthreads();
    }
    if (threadIdx.x == 0) g_Ksum[b * DD + m] = red[0];
}

// ---------------------------------------------------------------------------
// K2 (bf16): KXp[s][b][d][e] = sum_{n in split} Kf[d][n]*x[e][n]
// Block 64x128(e), Kchunk=64 halves, K=512/split (8 iters). grid (4, 8, 8)=256.
// smem u32 tiles: As32[64][36] (Kf pairs), Bs32[128][36] (x->bf16 pairs).
// Buf=6912 u32; double buffer 55,296 B. Ping-pong, one sync per iter.
// ---------------------------------------------------------------------------
#define K2_BUF 6912
__global__ __launch_bounds__(256) void k2_kx(const float* __restrict__ x)
{
    extern __shared__ unsigned su[];
    const int e0 = blockIdx.x * 128, b = blockIdx.y, sp = blockIdx.z;
    const int nbase = sp * (NN / KSPLIT);
    const int tid = threadIdx.x, wid = tid >> 5, lane = tid & 31;
    const int lrow = lane >> 2, lcol = lane & 3;
    const int m0w = (wid >> 2) * 32, e0w = (wid & 3) * 32;

    float acc[2][4][4];
    #pragma unroll
    for (int i = 0; i < 2; i++)
        #pragma unroll
        for (int j = 0; j < 4; j++)
            #pragma unroll
            for (int u = 0; u < 4; u++) acc[i][j][u] = 0.f;

    const __nv_bfloat16* kf = g_Kf + (size_t)b * DD * NN + nbase;
    const float* xb = x + (size_t)b * CC * NN + nbase;
    const int ad = tid >> 3, ach = tid & 7;         // A: row ad/ad+32, uint4 chunk ach
    const int be = tid >> 4, bf4 = tid & 15;        // B: rows be,+16.., float4 chunk bf4

    uint4 pa[2];
    unsigned pbu[8][2];   // 8 rows-slices x (2 u32 = 4 halves)... actually per-row 1 f4
    auto ldTiles = [&](int k0) {
        pa[0] = *(const uint4*)(kf + (size_t)ad * NN + k0 + ach * 8);
        pa[1] = *(const uint4*)(kf + (size_t)(ad + 32) * NN + k0 + ach * 8);
        #pragma unroll
        for (int r = 0; r < 8; r++) {
            float4 v = *(const float4*)(xb + (size_t)(e0 + be + 16 * r) * NN + k0 + bf4 * 4);
            pbu[r][0] = packbf(v.x, v.y);
            pbu[r][1] = packbf(v.z, v.w);
        }
    };
    auto stTiles = [&](unsigned* buf) {
        unsigned* As = buf; unsigned* Bs = buf + 2304;
        *(uint4*)(As + ad * 36 + ach * 4)        = pa[0];
        *(uint4*)(As + (ad + 32) * 36 + ach * 4) = pa[1];
        #pragma unroll
        for (int r = 0; r < 8; r++) {
            Bs[(be + 16 * r) * 36 + bf4 * 2]     = pbu[r][0];
            Bs[(be + 16 * r) * 36 + bf4 * 2 + 1] = pbu[r][1];
        }
    };

    ldTiles(0);
    stTiles(su);
    __syncthreads();

    int ph = 0;
    for (int k0 = 0; k0 < NN / KSPLIT; k0 += 64, ph ^= 1) {
        unsigned* cur = su + ph * K2_BUF;
        unsigned* nxt = su + (ph ^ 1) * K2_BUF;
        const bool more = (k0 + 64 < NN / KSPLIT);
        if (more) ldTiles(k0 + 64);

        unsigned* As = cur; unsigned* Bs = cur + 2304;
        #pragma unroll
        for (int s = 0; s < 4; s++) {
            unsigned a[2][4], bb[4][2];
            #pragma unroll
            for (int i = 0; i < 2; i++) {
                int r0 = (m0w + 16 * i + lrow) * 36 + 8 * s + lcol;
                a[i][0] = As[r0];           a[i][1] = As[r0 + 288];
                a[i][2] = As[r0 + 4];       a[i][3] = As[r0 + 292];
            }
            #pragma unroll
            for (int j = 0; j < 4; j++) {
                int er = (e0w + 8 * j + lrow) * 36 + 8 * s + lcol;
                bb[j][0] = Bs[er]; bb[j][1] = Bs[er + 4];
            }
            #pragma unroll
            for (int i = 0; i < 2; i++)
                #pragma unroll
                for (int j = 0; j < 4; j++)
                    mma16(acc[i][j], a[i][0], a[i][1], a[i][2], a[i][3], bb[j][0], bb[j][1]);
        }
        if (more) stTiles(nxt);
        __syncthreads();
    }

    float* dst = g_KXp + (size_t)(sp * BB + b) * DD * CC;
    #pragma unroll
    for (int i = 0; i < 2; i++) {
        int d = m0w + 16 * i + lrow;
        #pragma unroll
        for (int j = 0; j < 4; j++) {
            int e = e0 + e0w + 8 * j + 2 * lcol;
            float2 v0 = { acc[i][j][0], acc[i][j][1] };
            *(float2*)(dst + (size_t)d * CC + e) = v0;
            float2 v1 = { acc[i][j][2], acc[i][j][3] };
            *(float2*)(dst + (size_t)(d + 8) * CC + e) = v1;
        }
    }
}

// ---------------------------------------------------------------------------
// sumKX: g_KX = sum over KSPLIT of g_KXp. 65536 float4, grid 256.
// ---------------------------------------------------------------------------
__global__ __launch_bounds__(256) void k_sumkx()
{
    const int i = blockIdx.x * 256 + threadIdx.x;
    const int stride = BB * DD * CC / 4;
    const float4* p = (const float4*)g_KXp;
    float4 v[KSPLIT];
    #pragma unroll
    for (int sp = 0; sp < KSPLIT; sp++) v[sp] = p[(size_t)sp * stride + i];
    float4 s = v[0];
    #pragma unroll
    for (int sp = 1; sp < KSPLIT; sp++) {
        s.x += v[sp].x; s.y += v[sp].y; s.z += v[sp].z; s.w += v[sp].w;
    }
    ((float4*)g_KX)[i] = s;
}

// ---------------------------------------------------------------------------
// K3 (tf32): KVp[sp][b][d][c] = sum_{e in 128-split} KX[d][e]*wv[c][e]
// Block 64x128(c), K=128 (4 chunks). grid (4, 8, ESPLIT=4) = 128.
// ---------------------------------------------------------------------------
__global__ __launch_bounds__(256) void k3_kv(const float* __restrict__ wv)
{
    const int c0 = blockIdx.x * 128, b = blockIdx.y, sp = blockIdx.z;
    const int ebase = sp * (CC / ESPLIT);
    __shared__ float As[64][36];
    __shared__ float Bs[128][36];
    const int tid = threadIdx.x, wid = tid >> 5, lane = tid & 31;
    const int lrow = lane >> 2, lcol = lane & 3;
    const int m0w = (wid >> 2) * 32, c0w = (wid & 3) * 32;

    float acc[2][4][4];
    #pragma unroll
    for (int i = 0; i < 2; i++)
        #pragma unroll
        for (int j = 0; j < 4; j++)
            #pragma unroll
            for (int u = 0; u < 4; u++) acc[i][j][u] = 0.f;

    const float* kx = g_KX + (size_t)b * DD * CC + ebase;
    const int arow = tid >> 3, ac4 = (tid & 7) * 4;

    for (int k0 = 0; k0 < CC / ESPLIT; k0 += 32) {
        {
            float4 v0 = *(const float4*)(kx + (size_t)arow * CC + k0 + ac4);
            float4 v1 = *(const float4*)(kx + (size_t)(arow + 32) * CC + k0 + ac4);
            #pragma unroll
            for (int u = 0; u < 4; u++) {
                As[arow][ac4 + u]      = tf32_rna(((const float*)&v0)[u]);
                As[arow + 32][ac4 + u] = tf32_rna(((const float*)&v1)[u]);
            }
            #pragma unroll
            for (int r = 0; r < 4; r++) {
                float4 v = *(const float4*)(wv +
                    (size_t)(c0 + arow + 32 * r) * CC + ebase + k0 + ac4);
                #pragma unroll
                for (int u = 0; u < 4; u++)
                    Bs[arow + 32 * r][ac4 + u] = tf32_rna(((const float*)&v)[u]);
            }
        }
        __syncthreads();
        #pragma unroll
        for (int s = 0; s < 4; s++) {
            float a[2][4], bb[4][2];
            #pragma unroll
            for (int i = 0; i < 2; i++) {
                int r0 = m0w + 16 * i + lrow, cc0 = 8 * s + lcol;
                a[i][0] = As[r0][cc0];     a[i][1] = As[r0 + 8][cc0];
                a[i][2] = As[r0][cc0 + 4]; a[i][3] = As[r0 + 8][cc0 + 4];
            }
            #pragma unroll
            for (int j = 0; j < 4; j++) {
                int cr = c0w + 8 * j + lrow;
                bb[j][0] = Bs[cr][8 * s + lcol]; bb[j][1] = Bs[cr][8 * s + lcol + 4];
            }
            #pragma unroll
            for (int i = 0; i < 2; i++)
                #pragma unroll
                for (int j = 0; j < 4; j++)
                    mma8(acc[i][j], a[i][0], a[i][1], a[i][2], a[i][3], bb[j][0], bb[j][1]);
        }
        __syncthreads();
    }

    float* dst = g_KVp + (size_t)(sp * BB + b) * DD * CC;
    #pragma unroll
    for (int i = 0; i < 2; i++) {
        int d = m0w + 16 * i + lrow;
        #pragma unroll
        for (int j = 0; j < 4; j++) {
            int c = c0 + c0w + 8 * j + 2 * lcol;
            float2 v0 = { acc[i][j][0], acc[i][j][1] };
            *(float2*)(dst + (size_t)d * CC + c) = v0;
            float2 v1 = { acc[i][j][2], acc[i][j][3] };
            *(float2*)(dst + (size_t)(d + 8) * CC + c) = v1;
        }
    }
}

// ---------------------------------------------------------------------------
// sumKV: KVT[b][c][d] (bf16) = sum_sp KVp[sp][b][d][c] + bv[c]*Ksum[b][d]
// grid (CC/128=4, BB) = 32 blocks, 256 thr. smem transpose 64x128.
// ---------------------------------------------------------------------------
__global__ __launch_bounds__(256) void k_sumkv(const float* __restrict__ bv)
{
    __shared__ float sm[64 * 133];
    const int c0 = blockIdx.x * 128, b = blockIdx.y;
    const int tid = threadIdx.x;

    #pragma unroll
    for (int r = 0; r < 8; r++) {
        int idx = tid + r * 256;        // 0..2047
        int d = idx >> 5, c4 = (idx & 31) * 4;
        float4 s = *(const float4*)(g_KVp + ((size_t)b * DD + d) * CC + c0 + c4);
        #pragma unroll
        for (int sp = 1; sp < ESPLIT; sp++) {
            float4 v = *(const float4*)(g_KVp +
                ((size_t)(sp * BB + b) * DD + d) * CC + c0 + c4);
            s.x += v.x; s.y += v.y; s.z += v.z; s.w += v.w;
        }
        float ks = g_Ksum[b * DD + d];
        float4 bvv = *(const float4*)(bv + c0 + c4);
        sm[d * 133 + c4 + 0] = s.x + bvv.x * ks;
        sm[d * 133 + c4 + 1] = s.y + bvv.y * ks;
        sm[d * 133 + c4 + 2] = s.z + bvv.z * ks;
        sm[d * 133 + c4 + 3] = s.w + bvv.w * ks;
    }
    __syncthreads();

    #pragma unroll
    for (int r = 0; r < 4; r++) {
        int idx = tid + r * 256;        // 0..1023
        int c = idx >> 3, dch = idx & 7;
        int d0 = dch * 8;
        unsigned w[4];
        #pragma unroll
        for (int u = 0; u < 4; u++)
            w[u] = packbf(sm[(d0 + 2 * u) * 133 + c], sm[(d0 + 2 * u + 1) * 133 + c]);
        uint4 vv; vv.x = w[0]; vv.y = w[1]; vv.z = w[2]; vv.w = w[3];
        *(uint4*)(g_KVT + ((size_t)b * CC + c0 + c) * DD + d0) = vv;
    }
}

// ---------------------------------------------------------------------------
// K4 (bf16): out[c][n] = x[c][n] + gamma*norm[n]*sum_d KVT[c][d]*Qf[d][n]
// Persistent over c: grid (32, 8). Bs = Qf^T built once (smem transpose),
// As = KVT tile per c-tile with register prefetch. 8 warps: 4Mx2N, warp 32x64.
// Static smem: As32[128*36] + Bs32[128*36] u32 + ksum/norm = ~37.6 KB.
// ---------------------------------------------------------------------------
__global__ __launch_bounds__(256) void k4_out(
    const float* __restrict__ x, const float* __restrict__ gamma,
    float* __restrict__ out)
{
    __shared__ __align__(16) unsigned As32[128 * 36];
    __shared__ __align__(16) unsigned Bs32[128 * 36];
    __shared__ float ksumS[64];
    __shared__ float normS[128];

    const int n0 = blockIdx.x * 128, b = blockIdx.y;
    const int tid = threadIdx.x, wid = tid >> 5, lane = tid & 31;
    const int lrow = lane >> 2, lcol = lane & 3;
    const int m0w = (wid >> 1) * 32, n0w = (wid & 1) * 64;

    const __nv_bfloat16* qf = g_Qf + (size_t)b * DD * NN;
    const __nv_bfloat16* kvt = g_KVT + (size_t)b * CC * DD;

    // Bs = Qf^T[n][d] (bf16 halves), built once. Row stride 36 u32 = 72 halves.
    __nv_bfloat16* Bsh = (__nv_bfloat16*)Bs32;
    #pragma unroll
    for (int r = 0; r < 4; r++) {
        int idx = tid + r * 256;            // 0..1023
        int d = idx >> 4, ch = idx & 15;    // 8-half chunk along n
        uint4 v = *(const uint4*)(qf + (size_t)d * NN + n0 + ch * 8);
        const __nv_bfloat16* hv = (const __nv_bfloat16*)&v;
        #pragma unroll
        for (int u = 0; u < 8; u++)
            Bsh[(ch * 8 + u) * 72 + d] = hv[u];
    }
    if (tid < 64) ksumS[tid] = g_Ksum[b * DD + tid] + 1e-10f;

    const int kvc = tid >> 1, kvch = (tid & 1) * 4;   // As-build coords (128 rows x 2)
    uint4 kvreg[4];
    auto ldKV = [&](int c0) {
        #pragma unroll
        for (int r = 0; r < 4; r++)
            kvreg[r] = *(const uint4*)(kvt + (size_t)(c0 + kvc + 128 * 0 + 0) * DD
                                       + 0);   // placeholder (overwritten below)
        // real loads: 128 rows x 8 chunks = 1024 uint4, 4 per thread
        #pragma unroll
        for (int r = 0; r < 4; r++) {
            int idx = tid + r * 256;
            int c = idx >> 3, ch = idx & 7;
            kvreg[r] = *(const uint4*)(kvt + (size_t)(c0 + c) * DD + ch * 8);
        }
    };
    auto stAs = [&]() {
        #pragma unroll
        for (int r = 0; r < 4; r++) {
            int idx = tid + r * 256;
            int c = idx >> 3, ch = idx & 7;
            *(uint4*)(As32 + c * 36 + ch * 4) = kvreg[r];
        }
    };

    ldKV(0);
    __syncthreads();

    if (tid < 128) {
        const __nv_bfloat16* brow = Bsh + tid * 72;
        float s = 0.f;
        #pragma unroll
        for (int d = 0; d < 64; d++)
            s = fmaf(__bfloat162float(brow[d]), ksumS[d], s);
        normS[tid] = 1.0f / s;
    }
    const float g = gamma[0];

    for (int ct = 0; ct < CC / 128; ct++) {
        const int c0 = ct * 128;
        __syncthreads();    // prior mma readers of As done (1st iter: normS ready)
        stAs();
        __syncthreads();
        if (ct + 1 < CC / 128) ldKV(c0 + 128);   // overlap with mma below

        float acc[2][8][4];
        #pragma unroll
        for (int i = 0; i < 2; i++)
            #pragma unroll
            for (int j = 0; j < 8; j++)
                #pragma unroll
                for (int u = 0; u < 4; u++) acc[i][j][u] = 0.f;

        #pragma unroll
        for (int s = 0; s < 4; s++) {
            unsigned a[2][4], bb[8][2];
            #pragma unroll
            for (int i = 0; i < 2; i++) {
                int r0 = (m0w + 16 * i + lrow) * 36 + 8 * s + lcol;
                a[i][0] = As32[r0];       a[i][1] = As32[r0 + 288];
                a[i][2] = As32[r0 + 4];   a[i][3] = As32[r0 + 292];
            }
            #pragma unroll
            for (int j = 0; j < 8; j++) {
                int nr = (n0w + 8 * j + lrow) * 36 + 8 * s + lcol;
                bb[j][0] = Bs32[nr]; bb[j][1] = Bs32[nr + 4];
            }
            #pragma unroll
            for (int i = 0; i < 2; i++)
                #pragma unroll
                for (int j = 0; j < 8; j++)
                    mma16(acc[i][j], a[i][0], a[i][1], a[i][2], a[i][3], bb[j][0], bb[j][1]);
        }

        #pragma unroll
        for (int i = 0; i < 2; i++) {
            int c = c0 + m0w + 16 * i + lrow;
            #pragma unroll
            for (int j = 0; j < 8; j++) {
                int nl = n0w + 8 * j + 2 * lcol;
                int n = n0 + nl;
                float2 nr = *(float2*)&normS[nl];
                const float* xp0 = x + ((size_t)b * CC + c) * NN + n;
                float*       op0 = out + ((size_t)b * CC + c) * NN + n;
                float2 xv0 = *(const float2*)xp0;
                float2 o0 = { xv0.x + g * nr.x * acc[i][j][0],
                              xv0.y + g * nr.y * acc[i][j][1] };
                *(float2*)op0 = o0;
                const float* xp1 = x + ((size_t)b * CC + c + 8) * NN + n;
                float*       op1 = out + ((size_t)b * CC + c + 8) * NN + n;
                float2 xv1 = *(const float2*)xp1;
                float2 o1 = { xv1.x + g * nr.x * acc[i][j][2],
                              xv1.y + g * nr.y * acc[i][j][3] };
                *(float2*)op1 = o1;
            }
        }
    }
}

// ---------------------------------------------------------------------------
extern "C" void kernel_launch(void* const* d_in, const int* in_sizes, int n_in,
                              void* d_out, int out_size)
{
    const float* x     = (const float*)d_in[0];
    const float* wq    = (const float*)d_in[1];
    const float* bq    = (const float*)d_in[2];
    const float* wk    = (const float*)d_in[3];
    const float* bk    = (const float*)d_in[4];
    const float* wv    = (const float*)d_in[5];
    const float* bv    = (const float*)d_in[6];
    const float* gamma = (const float*)d_in[7];
    float* out = (float*)d_out;

    (void)in_sizes; (void)n_in; (void)out_size;

    cudaFuncSetAttribute(k2_kx, cudaFuncAttributeMaxDynamicSharedMemorySize, 55296);

    k1_qk  <<<dim3(NN / 128, BB),          256, 37888>>>(x, wq, bq, wk, bk);
    k_ksum <<<dim3(DD, BB),                256>>>();
    k2_kx  <<<dim3(CC / 128, BB, KSPLIT),  256, 55296>>>(x);
    k_sumkx<<<dim3(256),                   256>>>();
    k3_kv  <<<dim3(CC / 128, BB, ESPLIT),  256>>>(wv);
    k_sumkv<<<dim3(CC / 128, BB),          256>>>(bv);
    k4_out <<<dim3(NN / 128, BB),          256>>>(x, gamma, out);
}

// round 7
// speedup vs baseline: 3.6771x; 1.2080x over previous
#include <cuda_runtime.h>
#include <cuda_bf16.h>

#define BB 8
#define CC 512
#define DD 64
#define NN 4096
#define KSPLIT 8      // k2 split-K over n
#define ESPLIT 4      // k3 split over e

// Scratch (device globals). ~21 MB.
__device__ unsigned g_QfP[BB * 32 * NN];         // delu(Q) bf16 pairs: [b][d/2][n]
__device__ __nv_bfloat16 g_Kf[BB * DD * NN];     // delu(K)  [b][d][n]
__device__ float g_Ksum[BB * DD];
__device__ float g_KXp[KSPLIT * BB * DD * CC];   // split-K partials of Kf@X^T
__device__ float g_KX[BB * DD * CC];             // summed
__device__ float g_KVp[ESPLIT * BB * DD * CC];   // partials of KX@wv^T
__device__ __nv_bfloat16 g_KVT[BB * CC * DD];    // final KV, transposed [b][c][d]

__device__ __forceinline__ float delu_f(float v) {
    return v > 0.f ? fmaf(10.f, v, 1.f) : __expf(10.f * v);
}
__device__ __forceinline__ float tf32_rna(float f) {
    unsigned u;
    asm("cvt.rna.tf32.f32 %0, %1;" : "=r"(u) : "f"(f));
    return __uint_as_float(u);
}
__device__ __forceinline__ unsigned packbf(float lo, float hi) {
    __nv_bfloat162 h = __floats2bfloat162_rn(lo, hi);   // .x = lo = low half
    return *(unsigned*)&h;
}
// tf32 m16n8k8
__device__ __forceinline__ void mma8(float c[4], float a0, float a1, float a2, float a3,
                                     float b0, float b1) {
    unsigned A0 = __float_as_uint(a0), A1 = __float_as_uint(a1);
    unsigned A2 = __float_as_uint(a2), A3 = __float_as_uint(a3);
    unsigned B0 = __float_as_uint(b0), B1 = __float_as_uint(b1);
    asm volatile(
        "mma.sync.aligned.m16n8k8.row.col.f32.tf32.tf32.f32 "
        "{%0,%1,%2,%3}, {%4,%5,%6,%7}, {%8,%9}, {%0,%1,%2,%3};"
        : "+f"(c[0]), "+f"(c[1]), "+f"(c[2]), "+f"(c[3])
        : "r"(A0), "r"(A1), "r"(A2), "r"(A3), "r"(B0), "r"(B1));
}
// bf16 m16n8k16
__device__ __forceinline__ void mma16(float c[4], unsigned a0, unsigned a1,
                                      unsigned a2, unsigned a3,
                                      unsigned b0, unsigned b1) {
    asm volatile(
        "mma.sync.aligned.m16n8k16.row.col.f32.bf16.bf16.f32 "
        "{%0,%1,%2,%3}, {%4,%5,%6,%7}, {%8,%9}, {%0,%1,%2,%3};"
        : "+f"(c[0]), "+f"(c[1]), "+f"(c[2]), "+f"(c[3])
        : "r"(a0), "r"(a1), "r"(a2), "r"(a3), "r"(b0), "r"(b1));
}

// ---------------------------------------------------------------------------
// K1 (bf16, fused Q+K + Ksum): [wq;wk](128x512) @ X(512x4096) + bias -> delu
// Block 128x128, Kchunk=32 (2 k16 steps), 16 iters. 8 warps (2Mx4N), warp 64x32.
// grid (32, 8). Ping-pong double buffered.
// Buffer (u32): A[128][20] @0 (2560), B[16][136] @2560 (2176). Buf=4736; 37,888 B.
// Epilogue: Q -> g_QfP paired u32 (shfl-pair), K -> g_Kf bf16 + atomic Ksum.
// ---------------------------------------------------------------------------
#define K1_BUF 4736
__global__ __launch_bounds__(256, 2) void k1_qk(
    const float* __restrict__ x,  const float* __restrict__ wq,
    const float* __restrict__ bq, const float* __restrict__ wk,
    const float* __restrict__ bk)
{
    extern __shared__ unsigned su[];
    const int b = blockIdx.y;
    const int n0 = blockIdx.x * 128;
    const int tid = threadIdx.x, wid = tid >> 5, lane = tid & 31;
    const int lrow = lane >> 2, lcol = lane & 3;
    const int m0w = (wid >> 2) * 64, n0w = (wid & 3) * 32;

    float acc[4][4][4];
    #pragma unroll
    for (int i = 0; i < 4; i++)
        #pragma unroll
        for (int j = 0; j < 4; j++)
            #pragma unroll
            for (int u = 0; u < 4; u++) acc[i][j][u] = 0.f;

    const float* xb = x + (size_t)b * CC * NN;
    const int arow = tid >> 1, ak16 = (tid & 1) * 16;   // A: row, float offset
    const float* wrow = (arow < 64) ? (wq + (size_t)arow * CC)
                                    : (wk + (size_t)(arow - 64) * CC);

    float4 pa[4];           // 16 w floats
    float4 pb[2][2];        // B: 2 tasks x (2 k-rows)
    auto ldTiles = [&](int k0) {
        #pragma unroll
        for (int t = 0; t < 4; t++)
            pa[t] = *(const float4*)(wrow + k0 + ak16 + 4 * t);
        #pragma unroll
        for (int r = 0; r < 2; r++) {
            int idx = tid + r * 256;
            int kk = idx >> 5, nch = idx & 31;
            pb[r][0] = *(const float4*)(xb + (size_t)(k0 + 2 * kk) * NN + n0 + 4 * nch);
            pb[r][1] = *(const float4*)(xb + (size_t)(k0 + 2 * kk + 1) * NN + n0 + 4 * nch);
        }
    };
    auto stTiles = [&](unsigned* buf) {
        unsigned* A = buf; unsigned* B = buf + 2560;
        const float* f = (const float*)pa;
        unsigned wa[8];
        #pragma unroll
        for (int t = 0; t < 8; t++) wa[t] = packbf(f[2 * t], f[2 * t + 1]);
        *(uint4*)(A + arow * 20 + (tid & 1) * 8)     = *(uint4*)&wa[0];
        *(uint4*)(A + arow * 20 + (tid & 1) * 8 + 4) = *(uint4*)&wa[4];
        #pragma unroll
        for (int r = 0; r < 2; r++) {
            int idx = tid + r * 256;
            int kk = idx >> 5, nch = idx & 31;
            const float* fa = (const float*)&pb[r][0];
            const float* fb = (const float*)&pb[r][1];
            unsigned wb[4];
            #pragma unroll
            for (int t = 0; t < 4; t++) wb[t] = packbf(fa[t], fb[t]);
            *(uint4*)(B + kk * 136 + nch * 4) = *(uint4*)&wb[0];
        }
    };

    ldTiles(0);
    stTiles(su);
    __syncthreads();

    int ph = 0;
    for (int k0 = 0; k0 < CC; k0 += 32, ph ^= 1) {
        unsigned* cur = su + ph * K1_BUF;
        unsigned* nxt = su + (ph ^ 1) * K1_BUF;
        const bool more = (k0 + 32 < CC);
        if (more) ldTiles(k0 + 32);

        unsigned* A = cur; unsigned* B = cur + 2560;
        #pragma unroll
        for (int s = 0; s < 2; s++) {
            unsigned a[4][4], bb[4][2];
            #pragma unroll
            for (int i = 0; i < 4; i++) {
                int r0 = (m0w + 16 * i + lrow) * 20 + 8 * s;
                a[i][0] = A[r0 + lcol];       a[i][1] = A[r0 + 160 + lcol];
                a[i][2] = A[r0 + lcol + 4];   a[i][3] = A[r0 + 160 + lcol + 4];
            }
            #pragma unroll
            for (int j = 0; j < 4; j++) {
                int n = n0w + 8 * j + lrow;
                bb[j][0] = B[(8 * s + lcol) * 136 + n];
                bb[j][1] = B[(8 * s + lcol + 4) * 136 + n];
            }
            #pragma unroll
            for (int i = 0; i < 4; i++)
                #pragma unroll
                for (int j = 0; j < 4; j++)
                    mma16(acc[i][j], a[i][0], a[i][1], a[i][2], a[i][3], bb[j][0], bb[j][1]);
        }
        if (more) stTiles(nxt);
        __syncthreads();
    }

    const bool isK = (m0w == 64);       // uniform per warp
    #pragma unroll
    for (int i = 0; i < 4; i++) {
        int m = m0w + 16 * i + lrow;
        int mm = m & 63;
        float bi0 = isK ? bk[mm] : bq[mm];
        float bi1 = isK ? bk[mm + 8] : bq[mm + 8];
        float ks_lo = 0.f, ks_hi = 0.f;
        #pragma unroll
        for (int j = 0; j < 4; j++) {
            int n = n0 + n0w + 8 * j + 2 * lcol;
            float d0 = delu_f(acc[i][j][0] + bi0);
            float d1 = delu_f(acc[i][j][1] + bi0);
            float d2 = delu_f(acc[i][j][2] + bi1);
            float d3 = delu_f(acc[i][j][3] + bi1);
            if (isK) {
                __nv_bfloat16* dst = g_Kf + (size_t)b * DD * NN;
                *(__nv_bfloat162*)(dst + (size_t)mm * NN + n) = __floats2bfloat162_rn(d0, d1);
                *(__nv_bfloat162*)(dst + (size_t)(mm + 8) * NN + n) = __floats2bfloat162_rn(d2, d3);
                ks_lo += d0 + d1;
                ks_hi += d2 + d3;
            } else {
                // pair adjacent d rows via shfl (lanes lrow<->lrow+1 are +-4 apart)
                float e0 = __shfl_xor_sync(0xFFFFFFFFu, d0, 4);
                float e1 = __shfl_xor_sync(0xFFFFFFFFu, d1, 4);
                float e2 = __shfl_xor_sync(0xFFFFFFFFu, d2, 4);
                float e3 = __shfl_xor_sync(0xFFFFFFFFu, d3, 4);
                unsigned w0, w1;
                int dp;
                if ((lrow & 1) == 0) {          // pair (m, m+1)
                    w0 = packbf(d0, e0); w1 = packbf(d1, e1);
                    dp = mm >> 1;
                } else {                         // pair (m+8, m+9); recv = even lane's d2/d3
                    w0 = packbf(e2, d2); w1 = packbf(e3, d3);
                    dp = ((mm - 1) >> 1) + 4;
                }
                uint2 v; v.x = w0; v.y = w1;
                *(uint2*)(g_QfP + (size_t)b * 32 * NN + (size_t)dp * NN + n) = v;
            }
        }
        if (isK) {
            ks_lo += __shfl_xor_sync(0xFFFFFFFFu, ks_lo, 1);
            ks_lo += __shfl_xor_sync(0xFFFFFFFFu, ks_lo, 2);
            ks_hi += __shfl_xor_sync(0xFFFFFFFFu, ks_hi, 1);
            ks_hi += __shfl_xor_sync(0xFFFFFFFFu, ks_hi, 2);
            if (lcol == 0) {
                atomicAdd(&g_Ksum[b * DD + mm], ks_lo);
                atomicAdd(&g_Ksum[b * DD + mm + 8], ks_hi);
            }
        }
    }
}

// ---------------------------------------------------------------------------
// K2 (bf16): KXp[s][b][d][e] = sum_{n in split} Kf[d][n]*x[e][n]
// Block 64x128(e), Kchunk=64 halves, K=512/split (8 iters). grid (4, 8, 8)=256.
// Buf=6912 u32; double buffer 55,296 B. Ping-pong, one sync per iter.
// ---------------------------------------------------------------------------
#define K2_BUF 6912
__global__ __launch_bounds__(256, 2) void k2_kx(const float* __restrict__ x)
{
    extern __shared__ unsigned su[];
    const int e0 = blockIdx.x * 128, b = blockIdx.y, sp = blockIdx.z;
    const int nbase = sp * (NN / KSPLIT);
    const int tid = threadIdx.x, wid = tid >> 5, lane = tid & 31;
    const int lrow = lane >> 2, lcol = lane & 3;
    const int m0w = (wid >> 2) * 32, e0w = (wid & 3) * 32;

    float acc[2][4][4];
    #pragma unroll
    for (int i = 0; i < 2; i++)
        #pragma unroll
        for (int j = 0; j < 4; j++)
            #pragma unroll
            for (int u = 0; u < 4; u++) acc[i][j][u] = 0.f;

    const __nv_bfloat16* kf = g_Kf + (size_t)b * DD * NN + nbase;
    const float* xb = x + (size_t)b * CC * NN + nbase;
    const int ad = tid >> 3, ach = tid & 7;
    const int be = tid >> 4, bf4 = tid & 15;

    uint4 pa[2];
    unsigned pbu[8][2];
    auto ldTiles = [&](int k0) {
        pa[0] = *(const uint4*)(kf + (size_t)ad * NN + k0 + ach * 8);
        pa[1] = *(const uint4*)(kf + (size_t)(ad + 32) * NN + k0 + ach * 8);
        #pragma unroll
        for (int r = 0; r < 8; r++) {
            float4 v = *(const float4*)(xb + (size_t)(e0 + be + 16 * r) * NN + k0 + bf4 * 4);
            pbu[r][0] = packbf(v.x, v.y);
            pbu[r][1] = packbf(v.z, v.w);
        }
    };
    auto stTiles = [&](unsigned* buf) {
        unsigned* As = buf; unsigned* Bs = buf + 2304;
        *(uint4*)(As + ad * 36 + ach * 4)        = pa[0];
        *(uint4*)(As + (ad + 32) * 36 + ach * 4) = pa[1];
        #pragma unroll
        for (int r = 0; r < 8; r++) {
            Bs[(be + 16 * r) * 36 + bf4 * 2]     = pbu[r][0];
            Bs[(be + 16 * r) * 36 + bf4 * 2 + 1] = pbu[r][1];
        }
    };

    ldTiles(0);
    stTiles(su);
    __syncthreads();

    int ph = 0;
    for (int k0 = 0; k0 < NN / KSPLIT; k0 += 64, ph ^= 1) {
        unsigned* cur = su + ph * K2_BUF;
        unsigned* nxt = su + (ph ^ 1) * K2_BUF;
        const bool more = (k0 + 64 < NN / KSPLIT);
        if (more) ldTiles(k0 + 64);

        unsigned* As = cur; unsigned* Bs = cur + 2304;
        #pragma unroll
        for (int s = 0; s < 4; s++) {
            unsigned a[2][4], bb[4][2];
            #pragma unroll
            for (int i = 0; i < 2; i++) {
                int r0 = (m0w + 16 * i + lrow) * 36 + 8 * s + lcol;
                a[i][0] = As[r0];           a[i][1] = As[r0 + 288];
                a[i][2] = As[r0 + 4];       a[i][3] = As[r0 + 292];
            }
            #pragma unroll
            for (int j = 0; j < 4; j++) {
                int er = (e0w + 8 * j + lrow) * 36 + 8 * s + lcol;
                bb[j][0] = Bs[er]; bb[j][1] = Bs[er + 4];
            }
            #pragma unroll
            for (int i = 0; i < 2; i++)
                #pragma unroll
                for (int j = 0; j < 4; j++)
                    mma16(acc[i][j], a[i][0], a[i][1], a[i][2], a[i][3], bb[j][0], bb[j][1]);
        }
        if (more) stTiles(nxt);
        __syncthreads();
    }

    float* dst = g_KXp + (size_t)(sp * BB + b) * DD * CC;
    #pragma unroll
    for (int i = 0; i < 2; i++) {
        int d = m0w + 16 * i + lrow;
        #pragma unroll
        for (int j = 0; j < 4; j++) {
            int e = e0 + e0w + 8 * j + 2 * lcol;
            float2 v0 = { acc[i][j][0], acc[i][j][1] };
            *(float2*)(dst + (size_t)d * CC + e) = v0;
            float2 v1 = { acc[i][j][2], acc[i][j][3] };
            *(float2*)(dst + (size_t)(d + 8) * CC + e) = v1;
        }
    }
}

// ---------------------------------------------------------------------------
// sumKX: g_KX = sum over KSPLIT of g_KXp. 65536 float4, grid 256.
// ---------------------------------------------------------------------------
__global__ __launch_bounds__(256) void k_sumkx()
{
    const int i = blockIdx.x * 256 + threadIdx.x;
    const int stride = BB * DD * CC / 4;
    const float4* p = (const float4*)g_KXp;
    float4 v[KSPLIT];
    #pragma unroll
    for (int sp = 0; sp < KSPLIT; sp++) v[sp] = p[(size_t)sp * stride + i];
    float4 s = v[0];
    #pragma unroll
    for (int sp = 1; sp < KSPLIT; sp++) {
        s.x += v[sp].x; s.y += v[sp].y; s.z += v[sp].z; s.w += v[sp].w;
    }
    ((float4*)g_KX)[i] = s;
}

// ---------------------------------------------------------------------------
// K3 (tf32): KVp[sp][b][d][c] = sum_{e in 128-split} KX[d][e]*wv[c][e]
// Block 64x128(c), K=128 (4 chunks). grid (4, 8, ESPLIT=4) = 128.
// ---------------------------------------------------------------------------
__global__ __launch_bounds__(256) void k3_kv(const float* __restrict__ wv)
{
    const int c0 = blockIdx.x * 128, b = blockIdx.y, sp = blockIdx.z;
    const int ebase = sp * (CC / ESPLIT);
    __shared__ float As[64][36];
    __shared__ float Bs[128][36];
    const int tid = threadIdx.x, wid = tid >> 5, lane = tid & 31;
    const int lrow = lane >> 2, lcol = lane & 3;
    const int m0w = (wid >> 2) * 32, c0w = (wid & 3) * 32;

    float acc[2][4][4];
    #pragma unroll
    for (int i = 0; i < 2; i++)
        #pragma unroll
        for (int j = 0; j < 4; j++)
            #pragma unroll
            for (int u = 0; u < 4; u++) acc[i][j][u] = 0.f;

    const float* kx = g_KX + (size_t)b * DD * CC + ebase;
    const int arow = tid >> 3, ac4 = (tid & 7) * 4;

    for (int k0 = 0; k0 < CC / ESPLIT; k0 += 32) {
        {
            float4 v0 = *(const float4*)(kx + (size_t)arow * CC + k0 + ac4);
            float4 v1 = *(const float4*)(kx + (size_t)(arow + 32) * CC + k0 + ac4);
            #pragma unroll
            for (int u = 0; u < 4; u++) {
                As[arow][ac4 + u]      = tf32_rna(((const float*)&v0)[u]);
                As[arow + 32][ac4 + u] = tf32_rna(((const float*)&v1)[u]);
            }
            #pragma unroll
            for (int r = 0; r < 4; r++) {
                float4 v = *(const float4*)(wv +
                    (size_t)(c0 + arow + 32 * r) * CC + ebase + k0 + ac4);
                #pragma unroll
                for (int u = 0; u < 4; u++)
                    Bs[arow + 32 * r][ac4 + u] = tf32_rna(((const float*)&v)[u]);
            }
        }
        __syncthreads();
        #pragma unroll
        for (int s = 0; s < 4; s++) {
            float a[2][4], bb[4][2];
            #pragma unroll
            for (int i = 0; i < 2; i++) {
                int r0 = m0w + 16 * i + lrow, cc0 = 8 * s + lcol;
                a[i][0] = As[r0][cc0];     a[i][1] = As[r0 + 8][cc0];
                a[i][2] = As[r0][cc0 + 4]; a[i][3] = As[r0 + 8][cc0 + 4];
            }
            #pragma unroll
            for (int j = 0; j < 4; j++) {
                int cr = c0w + 8 * j + lrow;
                bb[j][0] = Bs[cr][8 * s + lcol]; bb[j][1] = Bs[cr][8 * s + lcol + 4];
            }
            #pragma unroll
            for (int i = 0; i < 2; i++)
                #pragma unroll
                for (int j = 0; j < 4; j++)
                    mma8(acc[i][j], a[i][0], a[i][1], a[i][2], a[i][3], bb[j][0], bb[j][1]);
        }
        __syncthreads();
    }

    float* dst = g_KVp + (size_t)(sp * BB + b) * DD * CC;
    #pragma unroll
    for (int i = 0; i < 2; i++) {
        int d = m0w + 16 * i + lrow;
        #pragma unroll
        for (int j = 0; j < 4; j++) {
            int c = c0 + c0w + 8 * j + 2 * lcol;
            float2 v0 = { acc[i][j][0], acc[i][j][1] };
            *(float2*)(dst + (size_t)d * CC + c) = v0;
            float2 v1 = { acc[i][j][2], acc[i][j][3] };
            *(float2*)(dst + (size_t)(d + 8) * CC + c) = v1;
        }
    }
}

// ---------------------------------------------------------------------------
// sumKV: KVT[b][c][d] (bf16) = sum_sp KVp[sp][b][d][c] + bv[c]*Ksum[b][d]
// grid (CC/128=4, BB) = 32 blocks, 256 thr. smem transpose 64x128.
// ---------------------------------------------------------------------------
__global__ __launch_bounds__(256) void k_sumkv(const float* __restrict__ bv)
{
    __shared__ float sm[64 * 133];
    const int c0 = blockIdx.x * 128, b = blockIdx.y;
    const int tid = threadIdx.x;

    #pragma unroll
    for (int r = 0; r < 8; r++) {
        int idx = tid + r * 256;
        int d = idx >> 5, c4 = (idx & 31) * 4;
        float4 s = *(const float4*)(g_KVp + ((size_t)b * DD + d) * CC + c0 + c4);
        #pragma unroll
        for (int sp = 1; sp < ESPLIT; sp++) {
            float4 v = *(const float4*)(g_KVp +
                ((size_t)(sp * BB + b) * DD + d) * CC + c0 + c4);
            s.x += v.x; s.y += v.y; s.z += v.z; s.w += v.w;
        }
        float ks = g_Ksum[b * DD + d];
        float4 bvv = *(const float4*)(bv + c0 + c4);
        sm[d * 133 + c4 + 0] = s.x + bvv.x * ks;
        sm[d * 133 + c4 + 1] = s.y + bvv.y * ks;
        sm[d * 133 + c4 + 2] = s.z + bvv.z * ks;
        sm[d * 133 + c4 + 3] = s.w + bvv.w * ks;
    }
    __syncthreads();

    #pragma unroll
    for (int r = 0; r < 4; r++) {
        int idx = tid + r * 256;
        int c = idx >> 3, dch = idx & 7;
        int d0 = dch * 8;
        unsigned w[4];
        #pragma unroll
        for (int u = 0; u < 4; u++)
            w[u] = packbf(sm[(d0 + 2 * u) * 133 + c], sm[(d0 + 2 * u + 1) * 133 + c]);
        uint4 vv; vv.x = w[0]; vv.y = w[1]; vv.z = w[2]; vv.w = w[3];
        *(uint4*)(g_KVT + ((size_t)b * CC + c0 + c) * DD + d0) = vv;
    }
}

// ---------------------------------------------------------------------------
// K4 (bf16): out[c][n] = x[c][n] + gamma*norm[n]*sum_d KVT[c][d]*QfP[d][n]
// Persistent over c: grid (32, 8). Bs = QfP tile (clean u32 copies, conflict-
// free). As = KVT tile per c-tile with register prefetch. 8 warps: 4Mx2N.
// ---------------------------------------------------------------------------
__global__ __launch_bounds__(256) void k4_out(
    const float* __restrict__ x, const float* __restrict__ gamma,
    float* __restrict__ out)
{
    __shared__ __align__(16) unsigned As32[128 * 36];
    __shared__ __align__(16) unsigned Bs32[128 * 36];
    __shared__ float ksumS[64];
    __shared__ float normS[128];

    const int n0 = blockIdx.x * 128, b = blockIdx.y;
    const int tid = threadIdx.x, wid = tid >> 5, lane = tid & 31;
    const int lrow = lane >> 2, lcol = lane & 3;
    const int m0w = (wid >> 1) * 32, n0w = (wid & 1) * 64;

    const unsigned* qfp = g_QfP + (size_t)b * 32 * NN;
    const __nv_bfloat16* kvt = g_KVT + (size_t)b * CC * DD;

    // Bs[n][d'] u32 (pairs along d) — conflict-free copy from paired Qf layout.
    #pragma unroll
    for (int r = 0; r < 16; r++) {
        int idx = tid + r * 256;
        int dlo = idx & 3, nlo = (idx >> 2) & 7;
        int dhi = (idx >> 5) & 7, nhi = idx >> 8;
        int dp = dhi * 4 + dlo, n = nhi * 8 + nlo;
        Bs32[n * 36 + dp] = qfp[(size_t)dp * NN + n0 + n];
    }
    if (tid < 64) ksumS[tid] = g_Ksum[b * DD + tid] + 1e-10f;

    uint4 kvreg[4];
    auto ldKV = [&](int c0) {
        #pragma unroll
        for (int r = 0; r < 4; r++) {
            int idx = tid + r * 256;
            int c = idx >> 3, ch = idx & 7;
            kvreg[r] = *(const uint4*)(kvt + (size_t)(c0 + c) * DD + ch * 8);
        }
    };
    auto stAs = [&]() {
        #pragma unroll
        for (int r = 0; r < 4; r++) {
            int idx = tid + r * 256;
            int c = idx >> 3, ch = idx & 7;
            *(uint4*)(As32 + c * 36 + ch * 4) = kvreg[r];
        }
    };

    ldKV(0);
    __syncthreads();

    if (tid < 128) {
        float s = 0.f;
        #pragma unroll
        for (int dp = 0; dp < 32; dp++) {
            float2 f = __bfloat1622float2(*(const __nv_bfloat162*)&Bs32[tid * 36 + dp]);
            s = fmaf(f.x, ksumS[2 * dp], s);
            s = fmaf(f.y, ksumS[2 * dp + 1], s);
        }
        normS[tid] = 1.0f / s;
    }
    const float g = gamma[0];

    for (int ct = 0; ct < CC / 128; ct++) {
        const int c0 = ct * 128;
        __syncthreads();    // prior mma readers of As done (1st iter: normS ready)
        stAs();
        __syncthreads();
        if (ct + 1 < CC / 128) ldKV(c0 + 128);   // overlap with mma below

        float acc[2][8][4];
        #pragma unroll
        for (int i = 0; i < 2; i++)
            #pragma unroll
            for (int j = 0; j < 8; j++)
                #pragma unroll
                for (int u = 0; u < 4; u++) acc[i][j][u] = 0.f;

        #pragma unroll
        for (int s = 0; s < 4; s++) {
            unsigned a[2][4], bb[8][2];
            #pragma unroll
            for (int i = 0; i < 2; i++) {
                int r0 = (m0w + 16 * i + lrow) * 36 + 8 * s + lcol;
                a[i][0] = As32[r0];       a[i][1] = As32[r0 + 288];
                a[i][2] = As32[r0 + 4];   a[i][3] = As32[r0 + 292];
            }
            #pragma unroll
            for (int j = 0; j < 8; j++) {
                int nr = (n0w + 8 * j + lrow) * 36 + 8 * s + lcol;
                bb[j][0] = Bs32[nr]; bb[j][1] = Bs32[nr + 4];
            }
            #pragma unroll
            for (int i = 0; i < 2; i++)
                #pragma unroll
                for (int j = 0; j < 8; j++)
                    mma16(acc[i][j], a[i][0], a[i][1], a[i][2], a[i][3], bb[j][0], bb[j][1]);
        }

        #pragma unroll
        for (int i = 0; i < 2; i++) {
            int c = c0 + m0w + 16 * i + lrow;
            #pragma unroll
            for (int j = 0; j < 8; j++) {
                int nl = n0w + 8 * j + 2 * lcol;
                int n = n0 + nl;
                float2 nr = *(float2*)&normS[nl];
                const float* xp0 = x + ((size_t)b * CC + c) * NN + n;
                float*       op0 = out + ((size_t)b * CC + c) * NN + n;
                float2 xv0 = *(const float2*)xp0;
                float2 o0 = { xv0.x + g * nr.x * acc[i][j][0],
                              xv0.y + g * nr.y * acc[i][j][1] };
                *(float2*)op0 = o0;
                const float* xp1 = x + ((size_t)b * CC + c + 8) * NN + n;
                float*       op1 = out + ((size_t)b * CC + c + 8) * NN + n;
                float2 xv1 = *(const float2*)xp1;
                float2 o1 = { xv1.x + g * nr.x * acc[i][j][2],
                              xv1.y + g * nr.y * acc[i][j][3] };
                *(float2*)op1 = o1;
            }
        }
    }
}

// ---------------------------------------------------------------------------
extern "C" void kernel_launch(void* const* d_in, const int* in_sizes, int n_in,
                              void* d_out, int out_size)
{
    const float* x     = (const float*)d_in[0];
    const float* wq    = (const float*)d_in[1];
    const float* bq    = (const float*)d_in[2];
    const float* wk    = (const float*)d_in[3];
    const float* bk    = (const float*)d_in[4];
    const float* wv    = (const float*)d_in[5];
    const float* bv    = (const float*)d_in[6];
    const float* gamma = (const float*)d_in[7];
    float* out = (float*)d_out;

    (void)in_sizes; (void)n_in; (void)out_size;

    cudaFuncSetAttribute(k1_qk, cudaFuncAttributeMaxDynamicSharedMemorySize, 37888);
    cudaFuncSetAttribute(k2_kx, cudaFuncAttributeMaxDynamicSharedMemorySize, 55296);

    void* ksum_ptr = nullptr;
    cudaGetSymbolAddress(&ksum_ptr, g_Ksum);
    cudaMemsetAsync(ksum_ptr, 0, BB * DD * sizeof(float));

    k1_qk  <<<dim3(NN / 128, BB),          256, 37888>>>(x, wq, bq, wk, bk);
    k2_kx  <<<dim3(CC / 128, BB, KSPLIT),  256, 55296>>>(x);
    k_sumkx<<<dim3(256),                   256>>>();
    k3_kv  <<<dim3(CC / 128, BB, ESPLIT),  256>>>(wv);
    k_sumkv<<<dim3(CC / 128, BB),          256>>>(bv);
    k4_out <<<dim3(NN / 128, BB),          256>>>(x, gamma, out);
}